// round 1
// baseline (speedup 1.0000x reference)
#include <cuda_runtime.h>
#include <math.h>

#define S_LEN 8192
#define DDIM  2048
#define LRATE 0.01f

// ---------------- scratch (static device memory; no allocation) -------------
// 5 big [S,D] buffers, aliased:
//   slot0 = k            (l2norm(x W_K^T))
//   slot1 = v  -> q      (reused after dy is formed)
//   slot2 = h1 -> dh1    (dsilu epilogue reads+writes same element)
//   slot3 = a1 -> a2
//   slot4 = dy
__device__ float g_scr[5ull * S_LEN * DDIM];
__device__ float g_gW1[DDIM * DDIM];
__device__ float g_gW2[DDIM * DDIM];
__device__ float g_fW1[DDIM * DDIM];
__device__ float g_fW2[DDIM * DDIM];
__device__ float g_gb1[DDIM], g_gb2[DDIM], g_fb1[DDIM], g_fb2[DDIM];
__device__ float g_meanx[DDIM];
__device__ float g_partial[64 * DDIM];
__device__ float g_alpha;

// ---------------- GEMM: C[M,N] = A*B with layout modes ----------------------
// LOAD_T: operand stored [X, K] row-major (needs transpose into smem)
// LOAD_D: operand stored [K, X] row-major (direct copy into smem)
enum { LOAD_T = 0, LOAD_D = 1 };
enum { EPI_NONE = 0, EPI_BIAS = 1, EPI_SILU = 2, EPI_DY = 3, EPI_DSILU = 4 };

template <int AMODE, int BMODE, int EPI, bool STORE_PRE>
__global__ __launch_bounds__(256, 2)
void gemm_kernel(const float* __restrict__ A, const float* __restrict__ B,
                 float* __restrict__ C, float* __restrict__ C2,
                 const float* __restrict__ bias, const float* __restrict__ aux,
                 int M, int N, int K, float scale)
{
    __shared__ float As[8][128];
    __shared__ float Bs[8][128];

    const int tid = threadIdx.x;
    const int m0 = blockIdx.y * 128;
    const int n0 = blockIdx.x * 128;
    const int tx = tid & 15;   // 0..15 -> 8 cols each
    const int ty = tid >> 4;   // 0..15 -> 8 rows each

    float acc[8][8];
#pragma unroll
    for (int i = 0; i < 8; i++)
#pragma unroll
        for (int j = 0; j < 8; j++) acc[i][j] = 0.f;

    for (int k0 = 0; k0 < K; k0 += 8) {
        // ---- load A tile ----
        if (AMODE == LOAD_T) {
            const int row = tid >> 1, kc = (tid & 1) * 4;
            const float4 a = *reinterpret_cast<const float4*>(
                &A[(size_t)(m0 + row) * K + k0 + kc]);
            As[kc + 0][row] = a.x; As[kc + 1][row] = a.y;
            As[kc + 2][row] = a.z; As[kc + 3][row] = a.w;
        } else {
            const int kr = tid >> 5, col = (tid & 31) * 4;
            *reinterpret_cast<float4*>(&As[kr][col]) =
                *reinterpret_cast<const float4*>(&A[(size_t)(k0 + kr) * M + m0 + col]);
        }
        // ---- load B tile ----
        if (BMODE == LOAD_T) {
            const int row = tid >> 1, kc = (tid & 1) * 4;
            const float4 b = *reinterpret_cast<const float4*>(
                &B[(size_t)(n0 + row) * K + k0 + kc]);
            Bs[kc + 0][row] = b.x; Bs[kc + 1][row] = b.y;
            Bs[kc + 2][row] = b.z; Bs[kc + 3][row] = b.w;
        } else {
            const int kr = tid >> 5, col = (tid & 31) * 4;
            *reinterpret_cast<float4*>(&Bs[kr][col]) =
                *reinterpret_cast<const float4*>(&B[(size_t)(k0 + kr) * N + n0 + col]);
        }
        __syncthreads();

#pragma unroll
        for (int kk = 0; kk < 8; kk++) {
            float af[8], bf[8];
            *reinterpret_cast<float4*>(&af[0]) = *reinterpret_cast<const float4*>(&As[kk][ty * 8]);
            *reinterpret_cast<float4*>(&af[4]) = *reinterpret_cast<const float4*>(&As[kk][ty * 8 + 4]);
            *reinterpret_cast<float4*>(&bf[0]) = *reinterpret_cast<const float4*>(&Bs[kk][tx * 8]);
            *reinterpret_cast<float4*>(&bf[4]) = *reinterpret_cast<const float4*>(&Bs[kk][tx * 8 + 4]);
#pragma unroll
            for (int i = 0; i < 8; i++)
#pragma unroll
                for (int j = 0; j < 8; j++)
                    acc[i][j] = fmaf(af[i], bf[j], acc[i][j]);
        }
        __syncthreads();
    }

    // ---- epilogue ----
#pragma unroll
    for (int i = 0; i < 8; i++) {
        const int r = m0 + ty * 8 + i;
#pragma unroll
        for (int j = 0; j < 8; j++) {
            const int c = n0 + tx * 8 + j;
            const size_t idx = (size_t)r * N + c;
            float v = acc[i][j];
            if (EPI == EPI_BIAS) {
                v += bias[c];
            } else if (EPI == EPI_SILU) {
                const float h = v + bias[c];
                const float sg = 1.f / (1.f + expf(-h));
                if (STORE_PRE) C2[idx] = h;
                v = h * sg;
            } else if (EPI == EPI_DY) {
                v = scale * (v + bias[c] - aux[idx]);
            } else if (EPI == EPI_DSILU) {
                const float h = aux[idx];
                const float sg = 1.f / (1.f + expf(-h));
                v = v * (sg * (1.f + h * (1.f - sg)));
            }
            C[idx] = v;
        }
    }
}

// ---------------- row l2-normalize (in place) -------------------------------
__global__ void rownorm_kernel(float* __restrict__ X, int ncols)
{
    const int r = blockIdx.x;
    float* row = X + (size_t)r * ncols;
    float s = 0.f;
    for (int i = threadIdx.x; i < ncols; i += 256) { const float v = row[i]; s += v * v; }
    __shared__ float red[256];
    red[threadIdx.x] = s;
    __syncthreads();
    for (int off = 128; off > 0; off >>= 1) {
        if (threadIdx.x < off) red[threadIdx.x] += red[threadIdx.x + off];
        __syncthreads();
    }
    const float inv = 1.f / fmaxf(sqrtf(red[0]), 1e-12f);
    for (int i = threadIdx.x; i < ncols; i += 256) row[i] *= inv;
}

// ---------------- deterministic column reduction (two pass) -----------------
__global__ void colsum_part(const float* __restrict__ X, int rows_per_chunk, int ncols)
{
    const int c = blockIdx.x * blockDim.x + threadIdx.x;
    const int r0 = blockIdx.y * rows_per_chunk;
    float s = 0.f;
    for (int r = 0; r < rows_per_chunk; r++) s += X[(size_t)(r0 + r) * ncols + c];
    g_partial[blockIdx.y * ncols + c] = s;
}

__global__ void colsum_fin(float* __restrict__ out, int nchunks, int ncols, float scale)
{
    const int c = blockIdx.x * blockDim.x + threadIdx.x;
    float s = 0.f;
    for (int i = 0; i < nchunks; i++) s += g_partial[i * ncols + c];
    out[c] = s * scale;
}

// ---------------- alpha gate ------------------------------------------------
__global__ void alpha_kernel(const float* __restrict__ aw, const float* __restrict__ ab)
{
    float s = 0.f;
    for (int i = threadIdx.x; i < DDIM; i += 256) s += g_meanx[i] * aw[i];
    __shared__ float red[256];
    red[threadIdx.x] = s;
    __syncthreads();
    for (int off = 128; off > 0; off >>= 1) {
        if (threadIdx.x < off) red[threadIdx.x] += red[threadIdx.x + off];
        __syncthreads();
    }
    if (threadIdx.x == 0) g_alpha = 1.f / (1.f + expf(-(red[0] + ab[0])));
}

// ---------------- fast-weight update ----------------------------------------
__global__ void fastw_kernel(const float* __restrict__ W, const float* __restrict__ g,
                             float* __restrict__ out, int n)
{
    const float a = g_alpha;
    const float oma = 1.f - a;
    for (int i = blockIdx.x * blockDim.x + threadIdx.x; i < n; i += gridDim.x * blockDim.x)
        out[i] = oma * W[i] - LRATE * g[i];
}

// ---------------- launch ----------------------------------------------------
extern "C" void kernel_launch(void* const* d_in, const int* in_sizes, int n_in,
                              void* d_out, int out_size)
{
    const float* x  = (const float*)d_in[0];
    const float* WQ = (const float*)d_in[1];
    const float* WK = (const float*)d_in[2];
    const float* WV = (const float*)d_in[3];
    const float* aw = (const float*)d_in[4];
    const float* ab = (const float*)d_in[5];
    const float* W1 = (const float*)d_in[6];
    const float* b1 = (const float*)d_in[7];
    const float* W2 = (const float*)d_in[8];
    const float* b2 = (const float*)d_in[9];
    float* out = (float*)d_out;

    float *scr, *gW1, *gW2, *fW1, *fW2, *gb1, *gb2, *fb1, *fb2, *meanx;
    cudaGetSymbolAddress((void**)&scr,   g_scr);
    cudaGetSymbolAddress((void**)&gW1,   g_gW1);
    cudaGetSymbolAddress((void**)&gW2,   g_gW2);
    cudaGetSymbolAddress((void**)&fW1,   g_fW1);
    cudaGetSymbolAddress((void**)&fW2,   g_fW2);
    cudaGetSymbolAddress((void**)&gb1,   g_gb1);
    cudaGetSymbolAddress((void**)&gb2,   g_gb2);
    cudaGetSymbolAddress((void**)&fb1,   g_fb1);
    cudaGetSymbolAddress((void**)&fb2,   g_fb2);
    cudaGetSymbolAddress((void**)&meanx, g_meanx);

    const size_t SD = (size_t)S_LEN * DDIM;
    float* Kb = scr;
    float* Vb = scr + SD;        // later reused as q
    float* H1 = scr + 2 * SD;    // later reused as dh1
    float* A1 = scr + 3 * SD;    // later reused as a2
    float* DY = scr + 4 * SD;
    float* Qb = Vb;
    float* DH = H1;
    float* A2 = A1;

    const dim3 blk(256);
    const dim3 gSD(DDIM / 128, S_LEN / 128);
    const dim3 gDD(DDIM / 128, DDIM / 128);
    const float dy_scale = 2.f / (float)((size_t)S_LEN * DDIM);

    // k = l2norm(x W_K^T), v = x W_V^T
    gemm_kernel<LOAD_T, LOAD_T, EPI_NONE, false><<<gSD, blk>>>(x, WK, Kb, nullptr, nullptr, nullptr, S_LEN, DDIM, DDIM, 0.f);
    gemm_kernel<LOAD_T, LOAD_T, EPI_NONE, false><<<gSD, blk>>>(x, WV, Vb, nullptr, nullptr, nullptr, S_LEN, DDIM, DDIM, 0.f);
    rownorm_kernel<<<S_LEN, 256>>>(Kb, DDIM);

    // alpha = sigmoid(mean_s(x) . alpha_w + alpha_b)
    colsum_part<<<dim3(DDIM / 256, 64), 256>>>(x, S_LEN / 64, DDIM);
    colsum_fin<<<DDIM / 256, 256>>>(meanx, 64, DDIM, 1.f / (float)S_LEN);
    alpha_kernel<<<1, 256>>>(aw, ab);

    // forward: h1 = k W1^T + b1 ; a1 = silu(h1) ; dy = 2/N * (a1 W2^T + b2 - v)
    gemm_kernel<LOAD_T, LOAD_T, EPI_SILU, true ><<<gSD, blk>>>(Kb, W1, A1, H1, b1, nullptr, S_LEN, DDIM, DDIM, 0.f);
    gemm_kernel<LOAD_T, LOAD_T, EPI_DY,   false><<<gSD, blk>>>(A1, W2, DY, nullptr, b2, Vb, S_LEN, DDIM, DDIM, dy_scale);

    // grads
    colsum_part<<<dim3(DDIM / 256, 64), 256>>>(DY, S_LEN / 64, DDIM);
    colsum_fin<<<DDIM / 256, 256>>>(gb2, 64, DDIM, 1.f);
    gemm_kernel<LOAD_D, LOAD_D, EPI_NONE, false><<<gDD, blk>>>(DY, A1, gW2, nullptr, nullptr, nullptr, DDIM, DDIM, S_LEN, 0.f);
    // dh1 = (dy W2) * silu'(h1)   (NN gemm, dsilu epilogue; DH aliases H1 elementwise)
    gemm_kernel<LOAD_T, LOAD_D, EPI_DSILU, false><<<gSD, blk>>>(DY, W2, DH, nullptr, nullptr, H1, S_LEN, DDIM, DDIM, 0.f);
    colsum_part<<<dim3(DDIM / 256, 64), 256>>>(DH, S_LEN / 64, DDIM);
    colsum_fin<<<DDIM / 256, 256>>>(gb1, 64, DDIM, 1.f);
    gemm_kernel<LOAD_D, LOAD_D, EPI_NONE, false><<<gDD, blk>>>(DH, Kb, gW1, nullptr, nullptr, nullptr, DDIM, DDIM, S_LEN, 0.f);

    // fast weights: (1-alpha)*p - lr*g
    fastw_kernel<<<256, 256>>>(W1, gW1, fW1, DDIM * DDIM);
    fastw_kernel<<<256, 256>>>(W2, gW2, fW2, DDIM * DDIM);
    fastw_kernel<<<2, 256>>>(b1, gb1, fb1, DDIM);
    fastw_kernel<<<2, 256>>>(b2, gb2, fb2, DDIM);

    // retrieve: q = l2norm(x W_Q^T); out = silu(q fW1^T + fb1) fW2^T + fb2
    gemm_kernel<LOAD_T, LOAD_T, EPI_NONE, false><<<gSD, blk>>>(x, WQ, Qb, nullptr, nullptr, nullptr, S_LEN, DDIM, DDIM, 0.f);
    rownorm_kernel<<<S_LEN, 256>>>(Qb, DDIM);
    gemm_kernel<LOAD_T, LOAD_T, EPI_SILU, false><<<gSD, blk>>>(Qb, fW1, A2, nullptr, fb1, nullptr, S_LEN, DDIM, DDIM, 0.f);
    gemm_kernel<LOAD_T, LOAD_T, EPI_BIAS, false><<<gSD, blk>>>(A2, fW2, out, nullptr, fb2, nullptr, S_LEN, DDIM, DDIM, 0.f);
}

// round 6
// speedup vs baseline: 1.6080x; 1.6080x over previous
#include <cuda_runtime.h>
#include <cuda_bf16.h>
#include <math.h>
#include <stdint.h>

#define S_LEN 8192
#define DDIM  2048
#define LRATE 0.01f

// ---------------- scratch (static device memory; no allocation) -------------
__device__ float g_scr[5ull * S_LEN * DDIM];
__device__ float g_gW1[DDIM * DDIM];
__device__ float g_gW2[DDIM * DDIM];
__device__ float g_fW1[DDIM * DDIM];
__device__ float g_fW2[DDIM * DDIM];
__device__ float g_gb1[DDIM], g_gb2[DDIM], g_fb1[DDIM], g_fb2[DDIM];
__device__ float g_meanx[DDIM];
__device__ float g_partial[64 * DDIM];
__device__ float g_alpha;

// ---------------- helpers -----------------------------------------------
__device__ __forceinline__ uint32_t smem_u32(const void* p) {
    uint32_t a;
    asm("{ .reg .u64 t; cvta.to.shared.u64 t, %1; cvt.u32.u64 %0, t; }" : "=r"(a) : "l"(p));
    return a;
}
__device__ __forceinline__ uint32_t pack_bf2(float f1, float f0) {
    uint32_t r;
    asm("cvt.rn.bf16x2.f32 %0, %1, %2;" : "=r"(r) : "f"(f1), "f"(f0));
    return r;
}
__device__ __forceinline__ float bf_lo_f(uint32_t p) { return __uint_as_float(p << 16); }
__device__ __forceinline__ float bf_hi_f(uint32_t p) { return __uint_as_float(p & 0xFFFF0000u); }

__device__ __forceinline__ void ldsm4(uint32_t (&r)[4], uint32_t addr) {
    asm volatile("ldmatrix.sync.aligned.m8n8.x4.shared.b16 {%0,%1,%2,%3}, [%4];"
                 : "=r"(r[0]), "=r"(r[1]), "=r"(r[2]), "=r"(r[3]) : "r"(addr));
}
__device__ __forceinline__ void mma16816(float (&c)[4], const uint32_t (&a)[4],
                                         uint32_t b0, uint32_t b1) {
    asm volatile(
        "mma.sync.aligned.m16n8k16.row.col.f32.bf16.bf16.f32 "
        "{%0,%1,%2,%3}, {%4,%5,%6,%7}, {%8,%9}, {%0,%1,%2,%3};"
        : "+f"(c[0]), "+f"(c[1]), "+f"(c[2]), "+f"(c[3])
        : "r"(a[0]), "r"(a[1]), "r"(a[2]), "r"(a[3]), "r"(b0), "r"(b1));
}

// swizzled byte offset within a [128 rows][32 bf16] tile (row stride 64B, 4x16B chunks)
__device__ __forceinline__ uint32_t swz(int row, int ch) {
    return (uint32_t)(row * 64 + ((ch ^ ((row >> 1) & 3)) << 4));
}

// ---------------- GEMM: C[M,N] = A[M,K] * B[N,K]^T ---------------------------
// MODE 0 (DIR): operand element [r,k] at src[r*ld + k]   (K contiguous)
// MODE 1 (TRN): operand element [r,k] at src[k*ld + r]   (R contiguous)
enum { MD_DIR = 0, MD_TRN = 1 };
enum { EPI_NONE = 0, EPI_BIAS = 1, EPI_SILU = 2, EPI_DY = 3, EPI_DSILU = 4 };

// dynamic smem: 2 stages x 32KB; within a stage: Ah@0, Al@8192, Bh@16384, Bl@24576
#define STAGE_BYTES 32768
#define SMEM_BYTES  (2 * STAGE_BYTES)

template <int MODE>
struct Stage {
    float v[16];
    __device__ __forceinline__ void load(const float* __restrict__ src, int ld,
                                         int org, int k0, int tid) {
        if (MODE == MD_DIR) {
#pragma unroll
            for (int i = 0; i < 2; i++) {
                const int f = tid + i * 256, row = f >> 2, ch = f & 3;
                const float4* p = reinterpret_cast<const float4*>(
                    src + (size_t)(org + row) * ld + k0 + ch * 8);
                const float4 x = p[0], y = p[1];
                v[i * 8 + 0] = x.x; v[i * 8 + 1] = x.y; v[i * 8 + 2] = x.z; v[i * 8 + 3] = x.w;
                v[i * 8 + 4] = y.x; v[i * 8 + 5] = y.y; v[i * 8 + 6] = y.z; v[i * 8 + 7] = y.w;
            }
        } else {
#pragma unroll
            for (int i = 0; i < 4; i++) {
                const int f = tid + i * 256, k = f >> 5, rq = f & 31;
                const float4 x = *reinterpret_cast<const float4*>(
                    src + (size_t)(k0 + k) * ld + org + rq * 4);
                v[i * 4 + 0] = x.x; v[i * 4 + 1] = x.y; v[i * 4 + 2] = x.z; v[i * 4 + 3] = x.w;
            }
        }
    }
    __device__ __forceinline__ void store(char* hi, char* lo, int tid) {
        if (MODE == MD_DIR) {
#pragma unroll
            for (int i = 0; i < 2; i++) {
                const int f = tid + i * 256, row = f >> 2, ch = f & 3;
                uint32_t h[4], l[4];
#pragma unroll
                for (int j = 0; j < 4; j++) {
                    const float f0 = v[i * 8 + 2 * j], f1 = v[i * 8 + 2 * j + 1];
                    h[j] = pack_bf2(f1, f0);
                    l[j] = pack_bf2(f1 - bf_hi_f(h[j]), f0 - bf_lo_f(h[j]));
                }
                const uint32_t off = swz(row, ch);
                *reinterpret_cast<uint4*>(hi + off) = make_uint4(h[0], h[1], h[2], h[3]);
                *reinterpret_cast<uint4*>(lo + off) = make_uint4(l[0], l[1], l[2], l[3]);
            }
        } else {
#pragma unroll
            for (int i = 0; i < 4; i++) {
                const int f = tid + i * 256, k = f >> 5, rq = f & 31;
                const int ch = k >> 3, kb = (k & 7) * 2;
#pragma unroll
                for (int j = 0; j < 4; j++) {
                    const float x = v[i * 4 + j];
                    const int row = rq * 4 + j;
                    __nv_bfloat16 hb = __float2bfloat16(x);
                    __nv_bfloat16 lb = __float2bfloat16(x - __bfloat162float(hb));
                    const uint32_t off = swz(row, ch) + kb;
                    *reinterpret_cast<__nv_bfloat16*>(hi + off) = hb;
                    *reinterpret_cast<__nv_bfloat16*>(lo + off) = lb;
                }
            }
        }
    }
};

template <int EPI, bool SP>
__device__ __forceinline__ float epi_apply(float a, int cc, size_t idx,
                                           const float* __restrict__ bias,
                                           const float* __restrict__ aux,
                                           float* __restrict__ C2, float scale) {
    if (EPI == EPI_BIAS) {
        a += bias[cc];
    } else if (EPI == EPI_SILU) {
        const float h = a + bias[cc];
        const float sg = 1.f / (1.f + expf(-h));
        if (SP) C2[idx] = h;
        a = h * sg;
    } else if (EPI == EPI_DY) {
        a = scale * (a + bias[cc] - aux[idx]);
    } else if (EPI == EPI_DSILU) {
        const float h = aux[idx];
        const float sg = 1.f / (1.f + expf(-h));
        a = a * (sg * (1.f + h * (1.f - sg)));
    }
    return a;
}

template <int AM, int BM, int EPI, bool SP>
__global__ __launch_bounds__(256, 1)
void tc_gemm(const float* __restrict__ A, const float* __restrict__ B,
             float* __restrict__ C, float* __restrict__ C2,
             const float* __restrict__ bias, const float* __restrict__ aux,
             int M, int N, int K, int lda, int ldb, float scale)
{
    extern __shared__ char smem[];
    const int tid = threadIdx.x;
    const int lane = tid & 31, wid = tid >> 5;
    const int wm = wid & 1, wn = wid >> 1;          // 2 x 4 warp grid: 64x32 per warp
    const int m0 = blockIdx.y * 128, n0 = blockIdx.x * 128;
    const uint32_t sbase = smem_u32(smem);

    float acc[4][4][4];
#pragma unroll
    for (int a = 0; a < 4; a++)
#pragma unroll
        for (int b = 0; b < 4; b++)
#pragma unroll
            for (int q = 0; q < 4; q++) acc[a][b][q] = 0.f;

    Stage<AM> sa;
    Stage<BM> sb;
    sa.load(A, lda, m0, 0, tid);
    sb.load(B, ldb, n0, 0, tid);
    sa.store(smem, smem + 8192, tid);
    sb.store(smem + 16384, smem + 24576, tid);
    __syncthreads();

    const int NC = K >> 5;
    for (int c = 0; c < NC; c++) {
        if (c + 1 < NC) {
            sa.load(A, lda, m0, (c + 1) * 32, tid);
            sb.load(B, ldb, n0, (c + 1) * 32, tid);
        }
        // ---- compute current stage ----
        const uint32_t st = sbase + (uint32_t)(c & 1) * STAGE_BYTES;
#pragma unroll
        for (int ks = 0; ks < 2; ks++) {
            uint32_t ah[4][4], al[4][4], bh[2][4], bl[2][4];
#pragma unroll
            for (int mt = 0; mt < 4; mt++) {
                const int row = wm * 64 + mt * 16 + (lane & 15);
                const int ch = ks * 2 + (lane >> 4);
                const uint32_t off = swz(row, ch);
                ldsm4(ah[mt], st + off);
                ldsm4(al[mt], st + 8192 + off);
            }
#pragma unroll
            for (int p = 0; p < 2; p++) {
                const int row = wn * 32 + p * 16 + ((lane >> 4) << 3) + (lane & 7);
                const int ch = ks * 2 + ((lane >> 3) & 1);
                const uint32_t off = swz(row, ch);
                ldsm4(bh[p], st + 16384 + off);
                ldsm4(bl[p], st + 24576 + off);
            }
#pragma unroll
            for (int mt = 0; mt < 4; mt++)
#pragma unroll
                for (int nt = 0; nt < 4; nt++) {
                    const int p = nt >> 1, q = (nt & 1) * 2;
                    mma16816(acc[mt][nt], ah[mt], bh[p][q], bh[p][q + 1]);
                    mma16816(acc[mt][nt], ah[mt], bl[p][q], bl[p][q + 1]);
                    mma16816(acc[mt][nt], al[mt], bh[p][q], bh[p][q + 1]);
                }
        }
        if (c + 1 < NC) {
            char* nb = smem + ((c + 1) & 1) * STAGE_BYTES;
            sa.store(nb, nb + 8192, tid);
            sb.store(nb + 16384, nb + 24576, tid);
        }
        __syncthreads();
    }

    // ---- epilogue ----
#pragma unroll
    for (int mt = 0; mt < 4; mt++) {
        const int r0 = m0 + wm * 64 + mt * 16 + (lane >> 2);
#pragma unroll
        for (int nt = 0; nt < 4; nt++) {
            const int cc = n0 + wn * 32 + nt * 8 + (lane & 3) * 2;
            const size_t i0 = (size_t)r0 * N + cc;
            const size_t i1 = (size_t)(r0 + 8) * N + cc;
            float2 t0, t1;
            t0.x = epi_apply<EPI, SP>(acc[mt][nt][0], cc,     i0,     bias, aux, C2, scale);
            t0.y = epi_apply<EPI, SP>(acc[mt][nt][1], cc + 1, i0 + 1, bias, aux, C2, scale);
            t1.x = epi_apply<EPI, SP>(acc[mt][nt][2], cc,     i1,     bias, aux, C2, scale);
            t1.y = epi_apply<EPI, SP>(acc[mt][nt][3], cc + 1, i1 + 1, bias, aux, C2, scale);
            *reinterpret_cast<float2*>(C + i0) = t0;
            *reinterpret_cast<float2*>(C + i1) = t1;
        }
    }
}

// ---------------- small kernels ----------------------------------------------
__global__ void rownorm_kernel(float* __restrict__ X, int ncols)
{
    const int r = blockIdx.x;
    float* row = X + (size_t)r * ncols;
    float s = 0.f;
    for (int i = threadIdx.x; i < ncols; i += 256) { const float v = row[i]; s += v * v; }
    __shared__ float red[256];
    red[threadIdx.x] = s;
    __syncthreads();
    for (int off = 128; off > 0; off >>= 1) {
        if (threadIdx.x < off) red[threadIdx.x] += red[threadIdx.x + off];
        __syncthreads();
    }
    const float inv = 1.f / fmaxf(sqrtf(red[0]), 1e-12f);
    for (int i = threadIdx.x; i < ncols; i += 256) row[i] *= inv;
}

__global__ void colsum_part(const float* __restrict__ X, int rows_per_chunk, int ncols)
{
    const int c = blockIdx.x * blockDim.x + threadIdx.x;
    const int r0 = blockIdx.y * rows_per_chunk;
    float s = 0.f;
    for (int r = 0; r < rows_per_chunk; r++) s += X[(size_t)(r0 + r) * ncols + c];
    g_partial[blockIdx.y * ncols + c] = s;
}

__global__ void colsum_fin(float* __restrict__ out, int nchunks, int ncols, float scale)
{
    const int c = blockIdx.x * blockDim.x + threadIdx.x;
    float s = 0.f;
    for (int i = 0; i < nchunks; i++) s += g_partial[i * ncols + c];
    out[c] = s * scale;
}

__global__ void alpha_kernel(const float* __restrict__ aw, const float* __restrict__ ab)
{
    float s = 0.f;
    for (int i = threadIdx.x; i < DDIM; i += 256) s += g_meanx[i] * aw[i];
    __shared__ float red[256];
    red[threadIdx.x] = s;
    __syncthreads();
    for (int off = 128; off > 0; off >>= 1) {
        if (threadIdx.x < off) red[threadIdx.x] += red[threadIdx.x + off];
        __syncthreads();
    }
    if (threadIdx.x == 0) g_alpha = 1.f / (1.f + expf(-(red[0] + ab[0])));
}

__global__ void fastw_kernel(const float* __restrict__ W, const float* __restrict__ g,
                             float* __restrict__ out, int n)
{
    const float a = g_alpha;
    const float oma = 1.f - a;
    for (int i = blockIdx.x * blockDim.x + threadIdx.x; i < n; i += gridDim.x * blockDim.x)
        out[i] = oma * W[i] - LRATE * g[i];
}

// ---------------- host-side launch helpers ----------------------------------
template <int AM, int BM, int EPI, bool SP>
static void run_gemm(const float* A, const float* B, float* C, float* C2,
                     const float* bias, const float* aux,
                     int M, int N, int K, int lda, int ldb, float scale)
{
    cudaFuncSetAttribute(tc_gemm<AM, BM, EPI, SP>,
                         cudaFuncAttributeMaxDynamicSharedMemorySize, SMEM_BYTES);
    tc_gemm<AM, BM, EPI, SP><<<dim3(N / 128, M / 128), 256, SMEM_BYTES>>>(
        A, B, C, C2, bias, aux, M, N, K, lda, ldb, scale);
}

extern "C" void kernel_launch(void* const* d_in, const int* in_sizes, int n_in,
                              void* d_out, int out_size)
{
    const float* x  = (const float*)d_in[0];
    const float* WQ = (const float*)d_in[1];
    const float* WK = (const float*)d_in[2];
    const float* WV = (const float*)d_in[3];
    const float* aw = (const float*)d_in[4];
    const float* ab = (const float*)d_in[5];
    const float* W1 = (const float*)d_in[6];
    const float* b1 = (const float*)d_in[7];
    const float* W2 = (const float*)d_in[8];
    const float* b2 = (const float*)d_in[9];
    float* out = (float*)d_out;

    float *scr, *gW1, *gW2, *fW1, *fW2, *gb1, *gb2, *fb1, *fb2, *meanx;
    cudaGetSymbolAddress((void**)&scr,   g_scr);
    cudaGetSymbolAddress((void**)&gW1,   g_gW1);
    cudaGetSymbolAddress((void**)&gW2,   g_gW2);
    cudaGetSymbolAddress((void**)&fW1,   g_fW1);
    cudaGetSymbolAddress((void**)&fW2,   g_fW2);
    cudaGetSymbolAddress((void**)&gb1,   g_gb1);
    cudaGetSymbolAddress((void**)&gb2,   g_gb2);
    cudaGetSymbolAddress((void**)&fb1,   g_fb1);
    cudaGetSymbolAddress((void**)&fb2,   g_fb2);
    cudaGetSymbolAddress((void**)&meanx, g_meanx);

    const size_t SD = (size_t)S_LEN * DDIM;
    float* Kb = scr;
    float* Vb = scr + SD;
    float* H1 = scr + 2 * SD;
    float* A1 = scr + 3 * SD;
    float* DY = scr + 4 * SD;
    float* Qb = Vb;
    float* DH = H1;
    float* A2 = A1;

    const float dy_scale = 2.f / (float)((size_t)S_LEN * DDIM);

    // k = l2norm(x W_K^T), v = x W_V^T
    run_gemm<MD_DIR, MD_DIR, EPI_NONE, false>(x, WK, Kb, nullptr, nullptr, nullptr, S_LEN, DDIM, DDIM, DDIM, DDIM, 0.f);
    run_gemm<MD_DIR, MD_DIR, EPI_NONE, false>(x, WV, Vb, nullptr, nullptr, nullptr, S_LEN, DDIM, DDIM, DDIM, DDIM, 0.f);
    rownorm_kernel<<<S_LEN, 256>>>(Kb, DDIM);

    // alpha
    colsum_part<<<dim3(DDIM / 256, 64), 256>>>(x, S_LEN / 64, DDIM);
    colsum_fin<<<DDIM / 256, 256>>>(meanx, 64, DDIM, 1.f / (float)S_LEN);
    alpha_kernel<<<1, 256>>>(aw, ab);

    // forward
    run_gemm<MD_DIR, MD_DIR, EPI_SILU, true >(Kb, W1, A1, H1, b1, nullptr, S_LEN, DDIM, DDIM, DDIM, DDIM, 0.f);
    run_gemm<MD_DIR, MD_DIR, EPI_DY,   false>(A1, W2, DY, nullptr, b2, Vb, S_LEN, DDIM, DDIM, DDIM, DDIM, dy_scale);

    // grads
    colsum_part<<<dim3(DDIM / 256, 64), 256>>>(DY, S_LEN / 64, DDIM);
    colsum_fin<<<DDIM / 256, 256>>>(gb2, 64, DDIM, 1.f);
    run_gemm<MD_TRN, MD_TRN, EPI_NONE, false>(DY, A1, gW2, nullptr, nullptr, nullptr, DDIM, DDIM, S_LEN, DDIM, DDIM, 0.f);
    run_gemm<MD_DIR, MD_TRN, EPI_DSILU, false>(DY, W2, DH, nullptr, nullptr, H1, S_LEN, DDIM, DDIM, DDIM, DDIM, 0.f);
    colsum_part<<<dim3(DDIM / 256, 64), 256>>>(DH, S_LEN / 64, DDIM);
    colsum_fin<<<DDIM / 256, 256>>>(gb1, 64, DDIM, 1.f);
    run_gemm<MD_TRN, MD_TRN, EPI_NONE, false>(DH, Kb, gW1, nullptr, nullptr, nullptr, DDIM, DDIM, S_LEN, DDIM, DDIM, 0.f);

    // fast weights
    fastw_kernel<<<256, 256>>>(W1, gW1, fW1, DDIM * DDIM);
    fastw_kernel<<<256, 256>>>(W2, gW2, fW2, DDIM * DDIM);
    fastw_kernel<<<2, 256>>>(b1, gb1, fb1, DDIM);
    fastw_kernel<<<2, 256>>>(b2, gb2, fb2, DDIM);

    // retrieve
    run_gemm<MD_DIR, MD_DIR, EPI_NONE, false>(x, WQ, Qb, nullptr, nullptr, nullptr, S_LEN, DDIM, DDIM, DDIM, DDIM, 0.f);
    rownorm_kernel<<<S_LEN, 256>>>(Qb, DDIM);
    run_gemm<MD_DIR, MD_DIR, EPI_SILU, false>(Qb, fW1, A2, nullptr, fb1, nullptr, S_LEN, DDIM, DDIM, DDIM, DDIM, 0.f);
    run_gemm<MD_DIR, MD_DIR, EPI_BIAS, false>(A2, fW2, out, nullptr, fb2, nullptr, S_LEN, DDIM, DDIM, DDIM, DDIM, 0.f);
}

// round 8
// speedup vs baseline: 2.8707x; 1.7853x over previous
#include <cuda_runtime.h>
#include <cuda_bf16.h>
#include <math.h>
#include <stdint.h>

#define S_LEN 8192
#define DDIM  2048
#define LRATE 0.01f

// ---------------- scratch (static device memory; no allocation) -------------
__device__ float g_scr[5ull * S_LEN * DDIM];
__device__ float g_gW1[DDIM * DDIM];
__device__ float g_gW2[DDIM * DDIM];
__device__ float g_fW1[DDIM * DDIM];
__device__ float g_fW2[DDIM * DDIM];
__device__ float g_gb1[DDIM], g_gb2[DDIM], g_fb1[DDIM], g_fb2[DDIM];
__device__ float g_meanx[DDIM];
__device__ float g_partial[64 * DDIM];
__device__ float g_alpha;

// ---------------- helpers -----------------------------------------------
__device__ __forceinline__ uint32_t smem_u32(const void* p) {
    uint32_t a;
    asm("{ .reg .u64 t; cvta.to.shared.u64 t, %1; cvt.u32.u64 %0, t; }" : "=r"(a) : "l"(p));
    return a;
}
__device__ __forceinline__ uint32_t f2tf(float f) {
    uint32_t r;
    asm("cvt.rna.tf32.f32 %0, %1;" : "=r"(r) : "f"(f));
    return r;
}
__device__ __forceinline__ void ldsm4(uint32_t (&r)[4], uint32_t addr) {
    asm volatile("ldmatrix.sync.aligned.m8n8.x4.shared.b16 {%0,%1,%2,%3}, [%4];"
                 : "=r"(r[0]), "=r"(r[1]), "=r"(r[2]), "=r"(r[3]) : "r"(addr));
}
__device__ __forceinline__ void mma_tf32(float (&c)[4], const uint32_t (&a)[4],
                                         uint32_t b0, uint32_t b1) {
    asm volatile(
        "mma.sync.aligned.m16n8k8.row.col.f32.tf32.tf32.f32 "
        "{%0,%1,%2,%3}, {%4,%5,%6,%7}, {%8,%9}, {%0,%1,%2,%3};"
        : "+f"(c[0]), "+f"(c[1]), "+f"(c[2]), "+f"(c[3])
        : "r"(a[0]), "r"(a[1]), "r"(a[2]), "r"(a[3]), "r"(b0), "r"(b1));
}

// tile: [128 rows][32 fp32], row stride 128B, 8 chunks of 16B, 8-way XOR swizzle
__device__ __forceinline__ uint32_t swz(int row, int ch) {
    return (uint32_t)(row * 128 + ((ch ^ (row & 7)) << 4));
}

// ---------------- GEMM: C[M,N] = A[M,K] * B[N,K]^T ---------------------------
// MODE 0 (DIR): operand element [r,k] at src[r*ld + k]   (K contiguous)
// MODE 1 (TRN): operand element [r,k] at src[k*ld + r]   (R contiguous)
enum { MD_DIR = 0, MD_TRN = 1 };
enum { EPI_NONE = 0, EPI_BIAS = 1, EPI_SILU = 2, EPI_DY = 3, EPI_DSILU = 4 };

// dynamic smem: 2 stages x 32KB; within a stage: A@0 (16KB), B@16384 (16KB)
#define STAGE_BYTES 32768
#define SMEM_BYTES  (2 * STAGE_BYTES)

template <int MODE>
struct Stage {
    float v[16];
    __device__ __forceinline__ void load(const float* __restrict__ src, int ld,
                                         int org, int k0, int tid) {
        if (MODE == MD_DIR) {
#pragma unroll
            for (int i = 0; i < 2; i++) {
                const int f = tid + i * 256, row = f >> 2, p = f & 3;
                const float4* ptr = reinterpret_cast<const float4*>(
                    src + (size_t)(org + row) * ld + k0 + p * 8);
                const float4 x = ptr[0], y = ptr[1];
                v[i * 8 + 0] = x.x; v[i * 8 + 1] = x.y; v[i * 8 + 2] = x.z; v[i * 8 + 3] = x.w;
                v[i * 8 + 4] = y.x; v[i * 8 + 5] = y.y; v[i * 8 + 6] = y.z; v[i * 8 + 7] = y.w;
            }
        } else {
            // thread -> (row r, 16B chunk kq); 4 strided coalesced scalar loads
#pragma unroll
            for (int i = 0; i < 4; i++) {
                const int f = tid + i * 256, r = f & 127, kq = f >> 7;
#pragma unroll
                for (int j = 0; j < 4; j++)
                    v[i * 4 + j] = src[(size_t)(k0 + kq * 4 + j) * ld + org + r];
            }
        }
    }
    __device__ __forceinline__ void store(char* buf, int tid) {
        if (MODE == MD_DIR) {
#pragma unroll
            for (int i = 0; i < 2; i++) {
                const int f = tid + i * 256, row = f >> 2, p = f & 3;
                uint32_t t[8];
#pragma unroll
                for (int j = 0; j < 8; j++) t[j] = f2tf(v[i * 8 + j]);
                *reinterpret_cast<uint4*>(buf + swz(row, 2 * p)) =
                    make_uint4(t[0], t[1], t[2], t[3]);
                *reinterpret_cast<uint4*>(buf + swz(row, 2 * p + 1)) =
                    make_uint4(t[4], t[5], t[6], t[7]);
            }
        } else {
#pragma unroll
            for (int i = 0; i < 4; i++) {
                const int f = tid + i * 256, r = f & 127, kq = f >> 7;
                uint32_t t[4];
#pragma unroll
                for (int j = 0; j < 4; j++) t[j] = f2tf(v[i * 4 + j]);
                *reinterpret_cast<uint4*>(buf + swz(r, kq)) =
                    make_uint4(t[0], t[1], t[2], t[3]);
            }
        }
    }
};

template <int EPI, bool SP>
__device__ __forceinline__ float epi_apply(float a, int cc, size_t idx,
                                           const float* __restrict__ bias,
                                           const float* __restrict__ aux,
                                           float* __restrict__ C2, float scale) {
    if (EPI == EPI_BIAS) {
        a += bias[cc];
    } else if (EPI == EPI_SILU) {
        const float h = a + bias[cc];
        const float sg = 1.f / (1.f + expf(-h));
        if (SP) C2[idx] = h;
        a = h * sg;
    } else if (EPI == EPI_DY) {
        a = scale * (a + bias[cc] - aux[idx]);
    } else if (EPI == EPI_DSILU) {
        const float h = aux[idx];
        const float sg = 1.f / (1.f + expf(-h));
        a = a * (sg * (1.f + h * (1.f - sg)));
    }
    return a;
}

template <int AM, int BM, int EPI, bool SP>
__global__ __launch_bounds__(256, 1)
void tc_gemm(const float* __restrict__ A, const float* __restrict__ B,
             float* __restrict__ C, float* __restrict__ C2,
             const float* __restrict__ bias, const float* __restrict__ aux,
             int M, int N, int K, int lda, int ldb, float scale)
{
    extern __shared__ char smem[];
    const int tid = threadIdx.x;
    const int lane = tid & 31, wid = tid >> 5;
    const int wm = wid & 1, wn = wid >> 1;          // 2 x 4 warp grid: 64x32 per warp
    const int m0 = blockIdx.y * 128, n0 = blockIdx.x * 128;
    const uint32_t sbase = smem_u32(smem);

    float acc[4][4][4];
#pragma unroll
    for (int a = 0; a < 4; a++)
#pragma unroll
        for (int b = 0; b < 4; b++)
#pragma unroll
            for (int q = 0; q < 4; q++) acc[a][b][q] = 0.f;

    Stage<AM> sa;
    Stage<BM> sb;
    sa.load(A, lda, m0, 0, tid);
    sb.load(B, ldb, n0, 0, tid);
    sa.store(smem, tid);
    sb.store(smem + 16384, tid);
    __syncthreads();

    // per-warp ldmatrix lane addressing components
    const int a_row = wm * 64 + ((lane >> 3) & 1) * 8 + (lane & 7);
    const int a_chb = (lane >> 4);                  // +0 or +1 chunk
    const int b_row = wn * 32 + (lane & 7);
    const int b_blk = lane >> 3;                    // chunk within half

    const int NC = K >> 5;
    for (int c = 0; c < NC; c++) {
        if (c + 1 < NC) {
            sa.load(A, lda, m0, (c + 1) * 32, tid);
            sb.load(B, ldb, n0, (c + 1) * 32, tid);
        }
        const uint32_t st = sbase + (uint32_t)(c & 1) * STAGE_BYTES;
#pragma unroll
        for (int h = 0; h < 2; h++) {
            uint32_t bf[4][4];
#pragma unroll
            for (int nt = 0; nt < 4; nt++)
                ldsm4(bf[nt], st + 16384u + swz(b_row + nt * 8, 4 * h + b_blk));
#pragma unroll
            for (int ss = 0; ss < 2; ss++) {
                const int s = 2 * h + ss;
                uint32_t af[4][4];
#pragma unroll
                for (int mt = 0; mt < 4; mt++)
                    ldsm4(af[mt], st + swz(a_row + mt * 16, 2 * s + a_chb));
#pragma unroll
                for (int mt = 0; mt < 4; mt++)
#pragma unroll
                    for (int nt = 0; nt < 4; nt++)
                        mma_tf32(acc[mt][nt], af[mt], bf[nt][2 * ss], bf[nt][2 * ss + 1]);
            }
        }
        if (c + 1 < NC) {
            char* nb = smem + ((c + 1) & 1) * STAGE_BYTES;
            sa.store(nb, tid);
            sb.store(nb + 16384, tid);
        }
        __syncthreads();
    }

    // ---- epilogue ----
#pragma unroll
    for (int mt = 0; mt < 4; mt++) {
        const int r0 = m0 + wm * 64 + mt * 16 + (lane >> 2);
#pragma unroll
        for (int nt = 0; nt < 4; nt++) {
            const int cc = n0 + wn * 32 + nt * 8 + (lane & 3) * 2;
            const size_t i0 = (size_t)r0 * N + cc;
            const size_t i1 = (size_t)(r0 + 8) * N + cc;
            float2 t0, t1;
            t0.x = epi_apply<EPI, SP>(acc[mt][nt][0], cc,     i0,     bias, aux, C2, scale);
            t0.y = epi_apply<EPI, SP>(acc[mt][nt][1], cc + 1, i0 + 1, bias, aux, C2, scale);
            t1.x = epi_apply<EPI, SP>(acc[mt][nt][2], cc,     i1,     bias, aux, C2, scale);
            t1.y = epi_apply<EPI, SP>(acc[mt][nt][3], cc + 1, i1 + 1, bias, aux, C2, scale);
            *reinterpret_cast<float2*>(C + i0) = t0;
            *reinterpret_cast<float2*>(C + i1) = t1;
        }
    }
}

// ---------------- small kernels ----------------------------------------------
__global__ void rownorm_kernel(float* __restrict__ X, int ncols)
{
    const int r = blockIdx.x;
    float* row = X + (size_t)r * ncols;
    float s = 0.f;
    for (int i = threadIdx.x; i < ncols; i += 256) { const float v = row[i]; s += v * v; }
    __shared__ float red[256];
    red[threadIdx.x] = s;
    __syncthreads();
    for (int off = 128; off > 0; off >>= 1) {
        if (threadIdx.x < off) red[threadIdx.x] += red[threadIdx.x + off];
        __syncthreads();
    }
    const float inv = 1.f / fmaxf(sqrtf(red[0]), 1e-12f);
    for (int i = threadIdx.x; i < ncols; i += 256) row[i] *= inv;
}

__global__ void colsum_part(const float* __restrict__ X, int rows_per_chunk, int ncols)
{
    const int c = blockIdx.x * blockDim.x + threadIdx.x;
    const int r0 = blockIdx.y * rows_per_chunk;
    float s = 0.f;
    for (int r = 0; r < rows_per_chunk; r++) s += X[(size_t)(r0 + r) * ncols + c];
    g_partial[blockIdx.y * ncols + c] = s;
}

__global__ void colsum_fin(float* __restrict__ out, int nchunks, int ncols, float scale)
{
    const int c = blockIdx.x * blockDim.x + threadIdx.x;
    float s = 0.f;
    for (int i = 0; i < nchunks; i++) s += g_partial[i * ncols + c];
    out[c] = s * scale;
}

__global__ void alpha_kernel(const float* __restrict__ aw, const float* __restrict__ ab)
{
    float s = 0.f;
    for (int i = threadIdx.x; i < DDIM; i += 256) s += g_meanx[i] * aw[i];
    __shared__ float red[256];
    red[threadIdx.x] = s;
    __syncthreads();
    for (int off = 128; off > 0; off >>= 1) {
        if (threadIdx.x < off) red[threadIdx.x] += red[threadIdx.x + off];
        __syncthreads();
    }
    if (threadIdx.x == 0) g_alpha = 1.f / (1.f + expf(-(red[0] + ab[0])));
}

__global__ void fastw_kernel(const float* __restrict__ W, const float* __restrict__ g,
                             float* __restrict__ out, int n)
{
    const float a = g_alpha;
    const float oma = 1.f - a;
    for (int i = blockIdx.x * blockDim.x + threadIdx.x; i < n; i += gridDim.x * blockDim.x)
        out[i] = oma * W[i] - LRATE * g[i];
}

// ---------------- host-side launch helpers ----------------------------------
template <int AM, int BM, int EPI, bool SP>
static void run_gemm(const float* A, const float* B, float* C, float* C2,
                     const float* bias, const float* aux,
                     int M, int N, int K, int lda, int ldb, float scale)
{
    cudaFuncSetAttribute(tc_gemm<AM, BM, EPI, SP>,
                         cudaFuncAttributeMaxDynamicSharedMemorySize, SMEM_BYTES);
    tc_gemm<AM, BM, EPI, SP><<<dim3(N / 128, M / 128), 256, SMEM_BYTES>>>(
        A, B, C, C2, bias, aux, M, N, K, lda, ldb, scale);
}

extern "C" void kernel_launch(void* const* d_in, const int* in_sizes, int n_in,
                              void* d_out, int out_size)
{
    const float* x  = (const float*)d_in[0];
    const float* WQ = (const float*)d_in[1];
    const float* WK = (const float*)d_in[2];
    const float* WV = (const float*)d_in[3];
    const float* aw = (const float*)d_in[4];
    const float* ab = (const float*)d_in[5];
    const float* W1 = (const float*)d_in[6];
    const float* b1 = (const float*)d_in[7];
    const float* W2 = (const float*)d_in[8];
    const float* b2 = (const float*)d_in[9];
    float* out = (float*)d_out;

    float *scr, *gW1, *gW2, *fW1, *fW2, *gb1, *gb2, *fb1, *fb2, *meanx;
    cudaGetSymbolAddress((void**)&scr,   g_scr);
    cudaGetSymbolAddress((void**)&gW1,   g_gW1);
    cudaGetSymbolAddress((void**)&gW2,   g_gW2);
    cudaGetSymbolAddress((void**)&fW1,   g_fW1);
    cudaGetSymbolAddress((void**)&fW2,   g_fW2);
    cudaGetSymbolAddress((void**)&gb1,   g_gb1);
    cudaGetSymbolAddress((void**)&gb2,   g_gb2);
    cudaGetSymbolAddress((void**)&fb1,   g_fb1);
    cudaGetSymbolAddress((void**)&fb2,   g_fb2);
    cudaGetSymbolAddress((void**)&meanx, g_meanx);

    const size_t SD = (size_t)S_LEN * DDIM;
    float* Kb = scr;
    float* Vb = scr + SD;
    float* H1 = scr + 2 * SD;
    float* A1 = scr + 3 * SD;
    float* DY = scr + 4 * SD;
    float* Qb = Vb;
    float* DH = H1;
    float* A2 = A1;

    const float dy_scale = 2.f / (float)((size_t)S_LEN * DDIM);

    // k = l2norm(x W_K^T), v = x W_V^T
    run_gemm<MD_DIR, MD_DIR, EPI_NONE, false>(x, WK, Kb, nullptr, nullptr, nullptr, S_LEN, DDIM, DDIM, DDIM, DDIM, 0.f);
    run_gemm<MD_DIR, MD_DIR, EPI_NONE, false>(x, WV, Vb, nullptr, nullptr, nullptr, S_LEN, DDIM, DDIM, DDIM, DDIM, 0.f);
    rownorm_kernel<<<S_LEN, 256>>>(Kb, DDIM);

    // alpha
    colsum_part<<<dim3(DDIM / 256, 64), 256>>>(x, S_LEN / 64, DDIM);
    colsum_fin<<<DDIM / 256, 256>>>(meanx, 64, DDIM, 1.f / (float)S_LEN);
    alpha_kernel<<<1, 256>>>(aw, ab);

    // forward
    run_gemm<MD_DIR, MD_DIR, EPI_SILU, true >(Kb, W1, A1, H1, b1, nullptr, S_LEN, DDIM, DDIM, DDIM, DDIM, 0.f);
    run_gemm<MD_DIR, MD_DIR, EPI_DY,   false>(A1, W2, DY, nullptr, b2, Vb, S_LEN, DDIM, DDIM, DDIM, DDIM, dy_scale);

    // grads
    colsum_part<<<dim3(DDIM / 256, 64), 256>>>(DY, S_LEN / 64, DDIM);
    colsum_fin<<<DDIM / 256, 256>>>(gb2, 64, DDIM, 1.f);
    run_gemm<MD_TRN, MD_TRN, EPI_NONE, false>(DY, A1, gW2, nullptr, nullptr, nullptr, DDIM, DDIM, S_LEN, DDIM, DDIM, 0.f);
    run_gemm<MD_DIR, MD_TRN, EPI_DSILU, false>(DY, W2, DH, nullptr, nullptr, H1, S_LEN, DDIM, DDIM, DDIM, DDIM, 0.f);
    colsum_part<<<dim3(DDIM / 256, 64), 256>>>(DH, S_LEN / 64, DDIM);
    colsum_fin<<<DDIM / 256, 256>>>(gb1, 64, DDIM, 1.f);
    run_gemm<MD_TRN, MD_TRN, EPI_NONE, false>(DH, Kb, gW1, nullptr, nullptr, nullptr, DDIM, DDIM, S_LEN, DDIM, DDIM, 0.f);

    // fast weights
    fastw_kernel<<<256, 256>>>(W1, gW1, fW1, DDIM * DDIM);
    fastw_kernel<<<256, 256>>>(W2, gW2, fW2, DDIM * DDIM);
    fastw_kernel<<<2, 256>>>(b1, gb1, fb1, DDIM);
    fastw_kernel<<<2, 256>>>(b2, gb2, fb2, DDIM);

    // retrieve
    run_gemm<MD_DIR, MD_DIR, EPI_NONE, false>(x, WQ, Qb, nullptr, nullptr, nullptr, S_LEN, DDIM, DDIM, DDIM, DDIM, 0.f);
    rownorm_kernel<<<S_LEN, 256>>>(Qb, DDIM);
    run_gemm<MD_DIR, MD_DIR, EPI_SILU, false>(Qb, fW1, A2, nullptr, fb1, nullptr, S_LEN, DDIM, DDIM, DDIM, DDIM, 0.f);
    run_gemm<MD_DIR, MD_DIR, EPI_BIAS, false>(A2, fW2, out, nullptr, fb2, nullptr, S_LEN, DDIM, DDIM, DDIM, DDIM, 0.f);
}

// round 9
// speedup vs baseline: 3.7403x; 1.3029x over previous
#include <cuda_runtime.h>
#include <cuda_fp16.h>
#include <math.h>
#include <stdint.h>

#define S_LEN 8192
#define DDIM  2048
#define LRATE 0.01f

// ---------------- scratch (static device memory; no allocation) -------------
__device__ float g_scr[5ull * S_LEN * DDIM];
__device__ float g_gW1[DDIM * DDIM];
__device__ float g_gW2[DDIM * DDIM];
__device__ float g_fW1[DDIM * DDIM];
__device__ float g_fW2[DDIM * DDIM];
__device__ float g_gb1[DDIM], g_gb2[DDIM], g_fb1[DDIM], g_fb2[DDIM];
__device__ float g_meanx[DDIM];
__device__ float g_partial[64 * DDIM];
__device__ float g_alpha;

// ---------------- helpers -----------------------------------------------
__device__ __forceinline__ uint32_t smem_u32(const void* p) {
    uint32_t a;
    asm("{ .reg .u64 t; cvta.to.shared.u64 t, %1; cvt.u32.u64 %0, t; }" : "=r"(a) : "l"(p));
    return a;
}
// pack two floats -> fp16x2 (lo = f0, hi = f1)
__device__ __forceinline__ uint32_t pack_h2(float f1, float f0) {
    uint32_t r;
    asm("cvt.rn.f16x2.f32 %0, %1, %2;" : "=r"(r) : "f"(f1), "f"(f0));
    return r;
}
__device__ __forceinline__ void ldsm4(uint32_t (&r)[4], uint32_t addr) {
    asm volatile("ldmatrix.sync.aligned.m8n8.x4.shared.b16 {%0,%1,%2,%3}, [%4];"
                 : "=r"(r[0]), "=r"(r[1]), "=r"(r[2]), "=r"(r[3]) : "r"(addr));
}
__device__ __forceinline__ void mma_f16(float (&c)[4], const uint32_t (&a)[4],
                                        uint32_t b0, uint32_t b1) {
    asm volatile(
        "mma.sync.aligned.m16n8k16.row.col.f32.f16.f16.f32 "
        "{%0,%1,%2,%3}, {%4,%5,%6,%7}, {%8,%9}, {%0,%1,%2,%3};"
        : "+f"(c[0]), "+f"(c[1]), "+f"(c[2]), "+f"(c[3])
        : "r"(a[0]), "r"(a[1]), "r"(a[2]), "r"(a[3]), "r"(b0), "r"(b1));
}

// tile: [128 rows][32 fp16], row stride 64B, 4 chunks of 16B, XOR swizzle
__device__ __forceinline__ uint32_t swz(int row, int ch) {
    return (uint32_t)(row * 64 + ((ch ^ ((row >> 1) & 3)) << 4));
}

// ---------------- GEMM: C[M,N] = A[M,K] * B[N,K]^T ---------------------------
// MODE 0 (DIR): operand element [r,k] at src[r*ld + k]   (K contiguous)
// MODE 1 (TRN): operand element [r,k] at src[k*ld + r]   (R contiguous)
enum { MD_DIR = 0, MD_TRN = 1 };
enum { EPI_NONE = 0, EPI_BIAS = 1, EPI_SILU = 2, EPI_DY = 3, EPI_DSILU = 4, EPI_SCALE = 5 };

// dynamic smem: 2 stages x 16KB; within a stage: A@0 (8KB), B@8192 (8KB)
#define STAGE_BYTES 16384
#define SMEM_BYTES  (2 * STAGE_BYTES)

template <int MODE>
struct Stage {
    float v[16];
    __device__ __forceinline__ void load(const float* __restrict__ src, int ld,
                                         int org, int k0, int tid) {
        if (MODE == MD_DIR) {
            // f -> (row = f>>2, chunk = f&3): 8 consecutive k values
#pragma unroll
            for (int i = 0; i < 2; i++) {
                const int f = tid + i * 256, row = f >> 2, ch = f & 3;
                const float4* ptr = reinterpret_cast<const float4*>(
                    src + (size_t)(org + row) * ld + k0 + ch * 8);
                const float4 x = ptr[0], y = ptr[1];
                v[i * 8 + 0] = x.x; v[i * 8 + 1] = x.y; v[i * 8 + 2] = x.z; v[i * 8 + 3] = x.w;
                v[i * 8 + 4] = y.x; v[i * 8 + 5] = y.y; v[i * 8 + 6] = y.z; v[i * 8 + 7] = y.w;
            }
        } else {
            // f -> (row r = f&127, chunk kq = f>>7): 8 strided k loads
#pragma unroll
            for (int i = 0; i < 2; i++) {
                const int f = tid + i * 256, r = f & 127, kq = f >> 7;
#pragma unroll
                for (int j = 0; j < 8; j++)
                    v[i * 8 + j] = src[(size_t)(k0 + kq * 8 + j) * ld + org + r];
            }
        }
    }
    __device__ __forceinline__ void store(char* buf, int tid) {
#pragma unroll
        for (int i = 0; i < 2; i++) {
            const int f = tid + i * 256;
            const int row = (MODE == MD_DIR) ? (f >> 2) : (f & 127);
            const int ch  = (MODE == MD_DIR) ? (f & 3)  : (f >> 7);
            uint32_t t[4];
#pragma unroll
            for (int j = 0; j < 4; j++)
                t[j] = pack_h2(v[i * 8 + 2 * j + 1], v[i * 8 + 2 * j]);
            *reinterpret_cast<uint4*>(buf + swz(row, ch)) = make_uint4(t[0], t[1], t[2], t[3]);
        }
    }
};

template <int EPI, bool SP>
__device__ __forceinline__ float epi_apply(float a, int cc, size_t idx,
                                           const float* __restrict__ bias,
                                           const float* __restrict__ aux,
                                           float* __restrict__ C2, float scale) {
    if (EPI == EPI_BIAS) {
        a += bias[cc];
    } else if (EPI == EPI_SILU) {
        const float h = a + bias[cc];
        const float sg = 1.f / (1.f + expf(-h));
        if (SP) C2[idx] = h;
        a = h * sg;
    } else if (EPI == EPI_DY) {
        a = scale * (a + bias[cc] - aux[idx]);
    } else if (EPI == EPI_DSILU) {
        const float h = aux[idx];
        const float sg = 1.f / (1.f + expf(-h));
        a = a * (sg * (1.f + h * (1.f - sg)));
    } else if (EPI == EPI_SCALE) {
        a *= scale;
    }
    return a;
}

template <int AM, int BM, int EPI, bool SP>
__global__ __launch_bounds__(256, 1)
void tc_gemm(const float* __restrict__ A, const float* __restrict__ B,
             float* __restrict__ C, float* __restrict__ C2,
             const float* __restrict__ bias, const float* __restrict__ aux,
             int M, int N, int K, int lda, int ldb, float scale)
{
    extern __shared__ char smem[];
    const int tid = threadIdx.x;
    const int lane = tid & 31, wid = tid >> 5;
    const int wm = wid & 1, wn = wid >> 1;          // 2 x 4 warp grid: 64x32 per warp
    const int m0 = blockIdx.y * 128, n0 = blockIdx.x * 128;
    const uint32_t sbase = smem_u32(smem);

    float acc[4][4][4];
#pragma unroll
    for (int a = 0; a < 4; a++)
#pragma unroll
        for (int b = 0; b < 4; b++)
#pragma unroll
            for (int q = 0; q < 4; q++) acc[a][b][q] = 0.f;

    Stage<AM> sa;
    Stage<BM> sb;
    sa.load(A, lda, m0, 0, tid);
    sb.load(B, ldb, n0, 0, tid);
    sa.store(smem, tid);
    sb.store(smem + 8192, tid);
    __syncthreads();

    const int NC = K >> 5;
    for (int c = 0; c < NC; c++) {
        if (c + 1 < NC) {
            sa.load(A, lda, m0, (c + 1) * 32, tid);
            sb.load(B, ldb, n0, (c + 1) * 32, tid);
        }
        const uint32_t st = sbase + (uint32_t)(c & 1) * STAGE_BYTES;
#pragma unroll
        for (int ks = 0; ks < 2; ks++) {
            uint32_t ah[4][4], bh[2][4];
#pragma unroll
            for (int mt = 0; mt < 4; mt++) {
                const int row = wm * 64 + mt * 16 + (lane & 15);
                const int ch = ks * 2 + (lane >> 4);
                ldsm4(ah[mt], st + swz(row, ch));
            }
#pragma unroll
            for (int p = 0; p < 2; p++) {
                const int row = wn * 32 + p * 16 + ((lane >> 4) << 3) + (lane & 7);
                const int ch = ks * 2 + ((lane >> 3) & 1);
                ldsm4(bh[p], st + 8192u + swz(row, ch));
            }
#pragma unroll
            for (int mt = 0; mt < 4; mt++)
#pragma unroll
                for (int nt = 0; nt < 4; nt++) {
                    const int p = nt >> 1, q = (nt & 1) * 2;
                    mma_f16(acc[mt][nt], ah[mt], bh[p][q], bh[p][q + 1]);
                }
        }
        if (c + 1 < NC) {
            char* nb = smem + ((c + 1) & 1) * STAGE_BYTES;
            sa.store(nb, tid);
            sb.store(nb + 8192, tid);
        }
        __syncthreads();
    }

    // ---- epilogue ----
#pragma unroll
    for (int mt = 0; mt < 4; mt++) {
        const int r0 = m0 + wm * 64 + mt * 16 + (lane >> 2);
#pragma unroll
        for (int nt = 0; nt < 4; nt++) {
            const int cc = n0 + wn * 32 + nt * 8 + (lane & 3) * 2;
            const size_t i0 = (size_t)r0 * N + cc;
            const size_t i1 = (size_t)(r0 + 8) * N + cc;
            float2 t0, t1;
            t0.x = epi_apply<EPI, SP>(acc[mt][nt][0], cc,     i0,     bias, aux, C2, scale);
            t0.y = epi_apply<EPI, SP>(acc[mt][nt][1], cc + 1, i0 + 1, bias, aux, C2, scale);
            t1.x = epi_apply<EPI, SP>(acc[mt][nt][2], cc,     i1,     bias, aux, C2, scale);
            t1.y = epi_apply<EPI, SP>(acc[mt][nt][3], cc + 1, i1 + 1, bias, aux, C2, scale);
            *reinterpret_cast<float2*>(C + i0) = t0;
            *reinterpret_cast<float2*>(C + i1) = t1;
        }
    }
}

// ---------------- small kernels ----------------------------------------------
__global__ void rownorm_kernel(float* __restrict__ X, int ncols)
{
    const int r = blockIdx.x;
    float* row = X + (size_t)r * ncols;
    float s = 0.f;
    for (int i = threadIdx.x; i < ncols; i += 256) { const float v = row[i]; s += v * v; }
    __shared__ float red[256];
    red[threadIdx.x] = s;
    __syncthreads();
    for (int off = 128; off > 0; off >>= 1) {
        if (threadIdx.x < off) red[threadIdx.x] += red[threadIdx.x + off];
        __syncthreads();
    }
    const float inv = 1.f / fmaxf(sqrtf(red[0]), 1e-12f);
    for (int i = threadIdx.x; i < ncols; i += 256) row[i] *= inv;
}

__global__ void colsum_part(const float* __restrict__ X, int rows_per_chunk, int ncols)
{
    const int c = blockIdx.x * blockDim.x + threadIdx.x;
    const int r0 = blockIdx.y * rows_per_chunk;
    float s = 0.f;
    for (int r = 0; r < rows_per_chunk; r++) s += X[(size_t)(r0 + r) * ncols + c];
    g_partial[blockIdx.y * ncols + c] = s;
}

__global__ void colsum_fin(float* __restrict__ out, int nchunks, int ncols, float scale)
{
    const int c = blockIdx.x * blockDim.x + threadIdx.x;
    float s = 0.f;
    for (int i = 0; i < nchunks; i++) s += g_partial[i * ncols + c];
    out[c] = s * scale;
}

__global__ void alpha_kernel(const float* __restrict__ aw, const float* __restrict__ ab)
{
    float s = 0.f;
    for (int i = threadIdx.x; i < DDIM; i += 256) s += g_meanx[i] * aw[i];
    __shared__ float red[256];
    red[threadIdx.x] = s;
    __syncthreads();
    for (int off = 128; off > 0; off >>= 1) {
        if (threadIdx.x < off) red[threadIdx.x] += red[threadIdx.x + off];
        __syncthreads();
    }
    if (threadIdx.x == 0) g_alpha = 1.f / (1.f + expf(-(red[0] + ab[0])));
}

__global__ void fastw_kernel(const float* __restrict__ W, const float* __restrict__ g,
                             float* __restrict__ out, int n)
{
    const float a = g_alpha;
    const float oma = 1.f - a;
    for (int i = blockIdx.x * blockDim.x + threadIdx.x; i < n; i += gridDim.x * blockDim.x)
        out[i] = oma * W[i] - LRATE * g[i];
}

// ---------------- host-side launch helpers ----------------------------------
template <int AM, int BM, int EPI, bool SP>
static void run_gemm(const float* A, const float* B, float* C, float* C2,
                     const float* bias, const float* aux,
                     int M, int N, int K, int lda, int ldb, float scale)
{
    cudaFuncSetAttribute(tc_gemm<AM, BM, EPI, SP>,
                         cudaFuncAttributeMaxDynamicSharedMemorySize, SMEM_BYTES);
    tc_gemm<AM, BM, EPI, SP><<<dim3(N / 128, M / 128), 256, SMEM_BYTES>>>(
        A, B, C, C2, bias, aux, M, N, K, lda, ldb, scale);
}

extern "C" void kernel_launch(void* const* d_in, const int* in_sizes, int n_in,
                              void* d_out, int out_size)
{
    const float* x  = (const float*)d_in[0];
    const float* WQ = (const float*)d_in[1];
    const float* WK = (const float*)d_in[2];
    const float* WV = (const float*)d_in[3];
    const float* aw = (const float*)d_in[4];
    const float* ab = (const float*)d_in[5];
    const float* W1 = (const float*)d_in[6];
    const float* b1 = (const float*)d_in[7];
    const float* W2 = (const float*)d_in[8];
    const float* b2 = (const float*)d_in[9];
    float* out = (float*)d_out;

    float *scr, *gW1, *gW2, *fW1, *fW2, *gb1, *gb2, *fb1, *fb2, *meanx;
    cudaGetSymbolAddress((void**)&scr,   g_scr);
    cudaGetSymbolAddress((void**)&gW1,   g_gW1);
    cudaGetSymbolAddress((void**)&gW2,   g_gW2);
    cudaGetSymbolAddress((void**)&fW1,   g_fW1);
    cudaGetSymbolAddress((void**)&fW2,   g_fW2);
    cudaGetSymbolAddress((void**)&gb1,   g_gb1);
    cudaGetSymbolAddress((void**)&gb2,   g_gb2);
    cudaGetSymbolAddress((void**)&fb1,   g_fb1);
    cudaGetSymbolAddress((void**)&fb2,   g_fb2);
    cudaGetSymbolAddress((void**)&meanx, g_meanx);

    const size_t SD = (size_t)S_LEN * DDIM;
    float* Kb = scr;
    float* Vb = scr + SD;
    float* H1 = scr + 2 * SD;
    float* A1 = scr + 3 * SD;
    float* DY = scr + 4 * SD;   // UNSCALED dy (O(1)); 2/N folded downstream
    float* Qb = Vb;
    float* DH = H1;             // UNSCALED dh
    float* A2 = A1;

    const float dy_scale = 2.f / (float)((size_t)S_LEN * DDIM);

    // k = l2norm(x W_K^T), v = x W_V^T
    run_gemm<MD_DIR, MD_DIR, EPI_NONE, false>(x, WK, Kb, nullptr, nullptr, nullptr, S_LEN, DDIM, DDIM, DDIM, DDIM, 0.f);
    run_gemm<MD_DIR, MD_DIR, EPI_NONE, false>(x, WV, Vb, nullptr, nullptr, nullptr, S_LEN, DDIM, DDIM, DDIM, DDIM, 0.f);
    rownorm_kernel<<<S_LEN, 256>>>(Kb, DDIM);

    // alpha
    colsum_part<<<dim3(DDIM / 256, 64), 256>>>(x, S_LEN / 64, DDIM);
    colsum_fin<<<DDIM / 256, 256>>>(meanx, 64, DDIM, 1.f / (float)S_LEN);
    alpha_kernel<<<1, 256>>>(aw, ab);

    // forward: h1, a1=silu(h1), dy_unscaled = a1 W2^T + b2 - v
    run_gemm<MD_DIR, MD_DIR, EPI_SILU, true >(Kb, W1, A1, H1, b1, nullptr, S_LEN, DDIM, DDIM, DDIM, DDIM, 0.f);
    run_gemm<MD_DIR, MD_DIR, EPI_DY,   false>(A1, W2, DY, nullptr, b2, Vb, S_LEN, DDIM, DDIM, DDIM, DDIM, 1.f);

    // grads (scale folded into epilogues / colsum_fin)
    colsum_part<<<dim3(DDIM / 256, 64), 256>>>(DY, S_LEN / 64, DDIM);
    colsum_fin<<<DDIM / 256, 256>>>(gb2, 64, DDIM, dy_scale);
    run_gemm<MD_TRN, MD_TRN, EPI_SCALE, false>(DY, A1, gW2, nullptr, nullptr, nullptr, DDIM, DDIM, S_LEN, DDIM, DDIM, dy_scale);
    // dh_unscaled = (dy_unscaled W2) * silu'(h1)
    run_gemm<MD_DIR, MD_TRN, EPI_DSILU, false>(DY, W2, DH, nullptr, nullptr, H1, S_LEN, DDIM, DDIM, DDIM, DDIM, 0.f);
    colsum_part<<<dim3(DDIM / 256, 64), 256>>>(DH, S_LEN / 64, DDIM);
    colsum_fin<<<DDIM / 256, 256>>>(gb1, 64, DDIM, dy_scale);
    run_gemm<MD_TRN, MD_TRN, EPI_SCALE, false>(DH, Kb, gW1, nullptr, nullptr, nullptr, DDIM, DDIM, S_LEN, DDIM, DDIM, dy_scale);

    // fast weights
    fastw_kernel<<<256, 256>>>(W1, gW1, fW1, DDIM * DDIM);
    fastw_kernel<<<256, 256>>>(W2, gW2, fW2, DDIM * DDIM);
    fastw_kernel<<<2, 256>>>(b1, gb1, fb1, DDIM);
    fastw_kernel<<<2, 256>>>(b2, gb2, fb2, DDIM);

    // retrieve
    run_gemm<MD_DIR, MD_DIR, EPI_NONE, false>(x, WQ, Qb, nullptr, nullptr, nullptr, S_LEN, DDIM, DDIM, DDIM, DDIM, 0.f);
    rownorm_kernel<<<S_LEN, 256>>>(Qb, DDIM);
    run_gemm<MD_DIR, MD_DIR, EPI_SILU, false>(Qb, fW1, A2, nullptr, fb1, nullptr, S_LEN, DDIM, DDIM, DDIM, DDIM, 0.f);
    run_gemm<MD_DIR, MD_DIR, EPI_BIAS, false>(A2, fW2, out, nullptr, fb2, nullptr, S_LEN, DDIM, DDIM, DDIM, DDIM, 0.f);
}

// round 12
// speedup vs baseline: 5.6470x; 1.5098x over previous
#include <cuda_runtime.h>
#include <cuda_fp16.h>
#include <math.h>
#include <stdint.h>

#define S_LEN 8192
#define DDIM  2048
#define LRATE 0.01f

// ---------------- scratch (static device memory; no allocation) -------------
__device__ float g_scr[5ull * S_LEN * DDIM];
__device__ float g_gW1[DDIM * DDIM];
__device__ float g_gW2[DDIM * DDIM];
__device__ float g_gb1[DDIM], g_gb2[DDIM], g_fb1[DDIM], g_fb2[DDIM];
__device__ float g_meanx[DDIM];
__device__ float g_partial[64 * DDIM];
__device__ float g_alpha;

// fp16 operand buffers
__device__ __half gh_x [(size_t)S_LEN * DDIM];
__device__ __half gh_K [(size_t)S_LEN * DDIM];
__device__ __half gh_Q [(size_t)S_LEN * DDIM];
__device__ __half gh_A1[(size_t)S_LEN * DDIM];   // reused as A2
__device__ __half gh_DY[(size_t)S_LEN * DDIM];
__device__ __half gh_DH[(size_t)S_LEN * DDIM];
__device__ __half gh_WQ[DDIM * DDIM];
__device__ __half gh_WK[DDIM * DDIM];
__device__ __half gh_WV[DDIM * DDIM];
__device__ __half gh_W1[DDIM * DDIM];
__device__ __half gh_W2[DDIM * DDIM];
__device__ __half gh_fW1[DDIM * DDIM];
__device__ __half gh_fW2[DDIM * DDIM];

// ---------------- helpers -----------------------------------------------
__device__ __forceinline__ uint32_t smem_u32(const void* p) {
    uint32_t a;
    asm("{ .reg .u64 t; cvta.to.shared.u64 t, %1; cvt.u32.u64 %0, t; }" : "=r"(a) : "l"(p));
    return a;
}
__device__ __forceinline__ uint32_t pack_h2(__half lo, __half hi) {
    __half2 h = __halves2half2(lo, hi);
    return *reinterpret_cast<uint32_t*>(&h);
}
__device__ __forceinline__ void ldsm4(uint32_t (&r)[4], uint32_t addr) {
    asm volatile("ldmatrix.sync.aligned.m8n8.x4.shared.b16 {%0,%1,%2,%3}, [%4];"
                 : "=r"(r[0]), "=r"(r[1]), "=r"(r[2]), "=r"(r[3]) : "r"(addr));
}
__device__ __forceinline__ void mma_f16(float (&c)[4], const uint32_t (&a)[4],
                                        uint32_t b0, uint32_t b1) {
    asm volatile(
        "mma.sync.aligned.m16n8k16.row.col.f32.f16.f16.f32 "
        "{%0,%1,%2,%3}, {%4,%5,%6,%7}, {%8,%9}, {%0,%1,%2,%3};"
        : "+f"(c[0]), "+f"(c[1]), "+f"(c[2]), "+f"(c[3])
        : "r"(a[0]), "r"(a[1]), "r"(a[2]), "r"(a[3]), "r"(b0), "r"(b1));
}

// tile: [128 rows][32 fp16], row stride 64B, 4 chunks of 16B, XOR swizzle
__device__ __forceinline__ uint32_t swz(int row, int ch) {
    return (uint32_t)(row * 64 + ((ch ^ ((row >> 1) & 3)) << 4));
}

// ---------------- GEMM: C[M,N] = A[M,K] * B[N,K]^T ---------------------------
enum { MD_DIR = 0, MD_TRN = 1 };
enum { EPI_NONE = 0, EPI_BIAS = 1, EPI_SILU = 2, EPI_DY = 3, EPI_DSILU = 4, EPI_SCALE = 5 };

// dynamic smem: 2 stages x 16KB; within a stage: A@0 (8KB), B@8192 (8KB)
#define STAGE_BYTES 16384
#define SMEM_BYTES  (2 * STAGE_BYTES)

template <int MODE>
struct Stage {
    uint32_t v[8];
    __device__ __forceinline__ void load(const __half* __restrict__ src, int ld,
                                         int org, int k0, int tid) {
        if (MODE == MD_DIR) {
#pragma unroll
            for (int i = 0; i < 2; i++) {
                const int f = tid + i * 256, row = f >> 2, ch = f & 3;
                const uint4 x = *reinterpret_cast<const uint4*>(
                    src + (size_t)(org + row) * ld + k0 + ch * 8);
                v[i * 4 + 0] = x.x; v[i * 4 + 1] = x.y; v[i * 4 + 2] = x.z; v[i * 4 + 3] = x.w;
            }
        } else {
#pragma unroll
            for (int i = 0; i < 2; i++) {
                const int f = tid + i * 256, r = f & 127, kq = f >> 7;
#pragma unroll
                for (int j = 0; j < 4; j++) {
                    const __half lo = src[(size_t)(k0 + kq * 8 + 2 * j)     * ld + org + r];
                    const __half hi = src[(size_t)(k0 + kq * 8 + 2 * j + 1) * ld + org + r];
                    v[i * 4 + j] = pack_h2(lo, hi);
                }
            }
        }
    }
    __device__ __forceinline__ void store(char* buf, int tid) {
#pragma unroll
        for (int i = 0; i < 2; i++) {
            const int f = tid + i * 256;
            const int row = (MODE == MD_DIR) ? (f >> 2) : (f & 127);
            const int ch  = (MODE == MD_DIR) ? (f & 3)  : (f >> 7);
            *reinterpret_cast<uint4*>(buf + swz(row, ch)) =
                make_uint4(v[i * 4 + 0], v[i * 4 + 1], v[i * 4 + 2], v[i * 4 + 3]);
        }
    }
};

template <int EPI, bool SP>
__device__ __forceinline__ float epi_apply(float a, int cc, size_t idx,
                                           const float* __restrict__ bias,
                                           const float* __restrict__ aux,
                                           float* __restrict__ C2, float scale) {
    if (EPI == EPI_BIAS) {
        a += bias[cc];
    } else if (EPI == EPI_SILU) {
        const float h = a + bias[cc];
        const float sg = 1.f / (1.f + expf(-h));
        if (SP) C2[idx] = h;
        a = h * sg;
    } else if (EPI == EPI_DY) {
        a = scale * (a + bias[cc] - aux[idx]);
    } else if (EPI == EPI_DSILU) {
        const float h = aux[idx];
        const float sg = 1.f / (1.f + expf(-h));
        a = a * (sg * (1.f + h * (1.f - sg)));
    } else if (EPI == EPI_SCALE) {
        a *= scale;
    }
    return a;
}

template <int AM, int BM, int EPI, bool SP, bool WC, bool WH>
__global__ __launch_bounds__(256, 2)
void tc_gemm(const __half* __restrict__ A, const __half* __restrict__ B,
             float* __restrict__ C, __half* __restrict__ Ch,
             float* __restrict__ C2,
             const float* __restrict__ bias, const float* __restrict__ aux,
             int M, int N, int K, int lda, int ldb, float scale)
{
    extern __shared__ char smem[];
    const int tid = threadIdx.x;
    const int lane = tid & 31, wid = tid >> 5;
    const int wm = wid & 1, wn = wid >> 1;          // 2 x 4 warp grid: 64x32 per warp
    const int m0 = blockIdx.y * 128, n0 = blockIdx.x * 128;
    const uint32_t sbase = smem_u32(smem);

    float acc[4][4][4];
#pragma unroll
    for (int a = 0; a < 4; a++)
#pragma unroll
        for (int b = 0; b < 4; b++)
#pragma unroll
            for (int q = 0; q < 4; q++) acc[a][b][q] = 0.f;

    Stage<AM> sa;
    Stage<BM> sb;
    sa.load(A, lda, m0, 0, tid);
    sb.load(B, ldb, n0, 0, tid);
    sa.store(smem, tid);
    sb.store(smem + 8192, tid);
    __syncthreads();

    const int NC = K >> 5;
    for (int c = 0; c < NC; c++) {
        if (c + 1 < NC) {
            sa.load(A, lda, m0, (c + 1) * 32, tid);
            sb.load(B, ldb, n0, (c + 1) * 32, tid);
        }
        const uint32_t st = sbase + (uint32_t)(c & 1) * STAGE_BYTES;
#pragma unroll
        for (int ks = 0; ks < 2; ks++) {
            uint32_t ah[4][4], bh[2][4];
#pragma unroll
            for (int mt = 0; mt < 4; mt++) {
                const int row = wm * 64 + mt * 16 + (lane & 15);
                const int ch = ks * 2 + (lane >> 4);
                ldsm4(ah[mt], st + swz(row, ch));
            }
#pragma unroll
            for (int p = 0; p < 2; p++) {
                const int row = wn * 32 + p * 16 + ((lane >> 4) << 3) + (lane & 7);
                const int ch = ks * 2 + ((lane >> 3) & 1);
                ldsm4(bh[p], st + 8192u + swz(row, ch));
            }
#pragma unroll
            for (int mt = 0; mt < 4; mt++)
#pragma unroll
                for (int nt = 0; nt < 4; nt++) {
                    const int p = nt >> 1, q = (nt & 1) * 2;
                    mma_f16(acc[mt][nt], ah[mt], bh[p][q], bh[p][q + 1]);
                }
        }
        if (c + 1 < NC) {
            char* nb = smem + ((c + 1) & 1) * STAGE_BYTES;
            sa.store(nb, tid);
            sb.store(nb + 8192, tid);
        }
        __syncthreads();
    }

    // ---- epilogue ----
#pragma unroll
    for (int mt = 0; mt < 4; mt++) {
        const int r0 = m0 + wm * 64 + mt * 16 + (lane >> 2);
#pragma unroll
        for (int nt = 0; nt < 4; nt++) {
            const int cc = n0 + wn * 32 + nt * 8 + (lane & 3) * 2;
            const size_t i0 = (size_t)r0 * N + cc;
            const size_t i1 = (size_t)(r0 + 8) * N + cc;
            float2 t0, t1;
            t0.x = epi_apply<EPI, SP>(acc[mt][nt][0], cc,     i0,     bias, aux, C2, scale);
            t0.y = epi_apply<EPI, SP>(acc[mt][nt][1], cc + 1, i0 + 1, bias, aux, C2, scale);
            t1.x = epi_apply<EPI, SP>(acc[mt][nt][2], cc,     i1,     bias, aux, C2, scale);
            t1.y = epi_apply<EPI, SP>(acc[mt][nt][3], cc + 1, i1 + 1, bias, aux, C2, scale);
            if (WC) {
                *reinterpret_cast<float2*>(C + i0) = t0;
                *reinterpret_cast<float2*>(C + i1) = t1;
            }
            if (WH) {
                __half2 h0 = __floats2half2_rn(t0.x, t0.y);
                __half2 h1 = __floats2half2_rn(t1.x, t1.y);
                *reinterpret_cast<__half2*>(Ch + i0) = h0;
                *reinterpret_cast<__half2*>(Ch + i1) = h1;
            }
        }
    }
}

// ---------------- small kernels ----------------------------------------------
__global__ void f2h_kernel(const float* __restrict__ in, __half* __restrict__ out, int n)
{
    for (int i = blockIdx.x * blockDim.x + threadIdx.x; i < n / 2; i += gridDim.x * blockDim.x) {
        const float2 v = reinterpret_cast<const float2*>(in)[i];
        reinterpret_cast<__half2*>(out)[i] = __floats2half2_rn(v.x, v.y);
    }
}

// row l2-normalize: read fp32, write fp16
__global__ void rownorm_h_kernel(const float* __restrict__ X, __half* __restrict__ out, int ncols)
{
    const int r = blockIdx.x;
    const float* row = X + (size_t)r * ncols;
    float s = 0.f;
    for (int i = threadIdx.x; i < ncols; i += 256) { const float v = row[i]; s += v * v; }
    __shared__ float red[256];
    red[threadIdx.x] = s;
    __syncthreads();
    for (int off = 128; off > 0; off >>= 1) {
        if (threadIdx.x < off) red[threadIdx.x] += red[threadIdx.x + off];
        __syncthreads();
    }
    const float inv = 1.f / fmaxf(sqrtf(red[0]), 1e-12f);
    __half* orow = out + (size_t)r * ncols;
    for (int i = threadIdx.x; i < ncols / 2; i += 256) {
        const float2 v = reinterpret_cast<const float2*>(row)[i];
        reinterpret_cast<__half2*>(orow)[i] = __floats2half2_rn(v.x * inv, v.y * inv);
    }
}

__global__ void colsum_part(const float* __restrict__ X, int rows_per_chunk, int ncols)
{
    const int c = blockIdx.x * blockDim.x + threadIdx.x;
    const int r0 = blockIdx.y * rows_per_chunk;
    float s = 0.f;
    for (int r = 0; r < rows_per_chunk; r++) s += X[(size_t)(r0 + r) * ncols + c];
    g_partial[blockIdx.y * ncols + c] = s;
}

__global__ void colsum_fin(float* __restrict__ out, int nchunks, int ncols, float scale)
{
    const int c = blockIdx.x * blockDim.x + threadIdx.x;
    float s = 0.f;
    for (int i = 0; i < nchunks; i++) s += g_partial[i * ncols + c];
    out[c] = s * scale;
}

__global__ void alpha_kernel(const float* __restrict__ aw, const float* __restrict__ ab)
{
    float s = 0.f;
    for (int i = threadIdx.x; i < DDIM; i += 256) s += g_meanx[i] * aw[i];
    __shared__ float red[256];
    red[threadIdx.x] = s;
    __syncthreads();
    for (int off = 128; off > 0; off >>= 1) {
        if (threadIdx.x < off) red[threadIdx.x] += red[threadIdx.x + off];
        __syncthreads();
    }
    if (threadIdx.x == 0) g_alpha = 1.f / (1.f + expf(-(red[0] + ab[0])));
}

// fast-weight matrices: write fp16 only (consumed exclusively as GEMM operands)
__global__ void fastw_h_kernel(const float* __restrict__ W, const float* __restrict__ g,
                               __half* __restrict__ out, int n)
{
    const float a = g_alpha;
    const float oma = 1.f - a;
    for (int i = blockIdx.x * blockDim.x + threadIdx.x; i < n / 2; i += gridDim.x * blockDim.x) {
        const float2 w = reinterpret_cast<const float2*>(W)[i];
        const float2 gg = reinterpret_cast<const float2*>(g)[i];
        reinterpret_cast<__half2*>(out)[i] =
            __floats2half2_rn(oma * w.x - LRATE * gg.x, oma * w.y - LRATE * gg.y);
    }
}

// fast-weight biases: fp32 (consumed as fp32 bias in epilogues)
__global__ void fastb_kernel(const float* __restrict__ W, const float* __restrict__ g,
                             float* __restrict__ out, int n)
{
    const float a = g_alpha;
    const float oma = 1.f - a;
    for (int i = blockIdx.x * blockDim.x + threadIdx.x; i < n; i += gridDim.x * blockDim.x)
        out[i] = oma * W[i] - LRATE * g[i];
}

// ---------------- host-side launch helpers ----------------------------------
template <int AM, int BM, int EPI, bool SP, bool WC, bool WH>
static void run_gemm(const __half* A, const __half* B, float* C, __half* Ch, float* C2,
                     const float* bias, const float* aux,
                     int M, int N, int K, int lda, int ldb, float scale)
{
    cudaFuncSetAttribute(tc_gemm<AM, BM, EPI, SP, WC, WH>,
                         cudaFuncAttributeMaxDynamicSharedMemorySize, SMEM_BYTES);
    tc_gemm<AM, BM, EPI, SP, WC, WH><<<dim3(N / 128, M / 128), 256, SMEM_BYTES>>>(
        A, B, C, Ch, C2, bias, aux, M, N, K, lda, ldb, scale);
}

extern "C" void kernel_launch(void* const* d_in, const int* in_sizes, int n_in,
                              void* d_out, int out_size)
{
    const float* x  = (const float*)d_in[0];
    const float* WQ = (const float*)d_in[1];
    const float* WK = (const float*)d_in[2];
    const float* WV = (const float*)d_in[3];
    const float* aw = (const float*)d_in[4];
    const float* ab = (const float*)d_in[5];
    const float* W1 = (const float*)d_in[6];
    const float* b1 = (const float*)d_in[7];
    const float* W2 = (const float*)d_in[8];
    const float* b2 = (const float*)d_in[9];
    float* out = (float*)d_out;

    float *scr, *gW1, *gW2, *gb1, *gb2, *fb1, *fb2, *meanx;
    cudaGetSymbolAddress((void**)&scr, g_scr);
    cudaGetSymbolAddress((void**)&gW1, g_gW1);
    cudaGetSymbolAddress((void**)&gW2, g_gW2);
    cudaGetSymbolAddress((void**)&gb1, g_gb1);
    cudaGetSymbolAddress((void**)&gb2, g_gb2);
    cudaGetSymbolAddress((void**)&fb1, g_fb1);
    cudaGetSymbolAddress((void**)&fb2, g_fb2);
    cudaGetSymbolAddress((void**)&meanx, g_meanx);

    __half *xh, *Kh, *Qh, *A1h, *DYh, *DHh, *WQh, *WKh, *WVh, *W1h, *W2h, *fW1h, *fW2h;
    cudaGetSymbolAddress((void**)&xh,  gh_x);
    cudaGetSymbolAddress((void**)&Kh,  gh_K);
    cudaGetSymbolAddress((void**)&Qh,  gh_Q);
    cudaGetSymbolAddress((void**)&A1h, gh_A1);
    cudaGetSymbolAddress((void**)&DYh, gh_DY);
    cudaGetSymbolAddress((void**)&DHh, gh_DH);
    cudaGetSymbolAddress((void**)&WQh, gh_WQ);
    cudaGetSymbolAddress((void**)&WKh, gh_WK);
    cudaGetSymbolAddress((void**)&WVh, gh_WV);
    cudaGetSymbolAddress((void**)&W1h, gh_W1);
    cudaGetSymbolAddress((void**)&W2h, gh_W2);
    cudaGetSymbolAddress((void**)&fW1h, gh_fW1);
    cudaGetSymbolAddress((void**)&fW2h, gh_fW2);

    const size_t SD = (size_t)S_LEN * DDIM;
    float* Kb = scr;            // fp32 k (pre-norm)
    float* Vb = scr + SD;       // fp32 v (aux for EPI_DY)
    float* H1 = scr + 2 * SD;   // fp32 pre-activation (aux for dsilu)
    float* DY = scr + 3 * SD;   // fp32 unscaled dy (colsum gb2)
    float* DH = scr + 4 * SD;   // fp32 unscaled dh (colsum gb1)
    float* Qb = Kb;             // reuse after Kh is produced

    const float dy_scale = 2.f / (float)((size_t)S_LEN * DDIM);
    const int SDn = (int)SD, DDn = DDIM * DDIM;

    // ---- one-time fp16 conversions of external operands ----
    f2h_kernel<<<256, 256>>>(x,  xh,  SDn);
    f2h_kernel<<<128, 256>>>(WQ, WQh, DDn);
    f2h_kernel<<<128, 256>>>(WK, WKh, DDn);
    f2h_kernel<<<128, 256>>>(WV, WVh, DDn);
    f2h_kernel<<<128, 256>>>(W1, W1h, DDn);
    f2h_kernel<<<128, 256>>>(W2, W2h, DDn);

    // k = x W_K^T (fp32), v = x W_V^T (fp32)
    run_gemm<MD_DIR, MD_DIR, EPI_NONE, false, true, false>(xh, WKh, Kb, nullptr, nullptr, nullptr, nullptr, S_LEN, DDIM, DDIM, DDIM, DDIM, 0.f);
    run_gemm<MD_DIR, MD_DIR, EPI_NONE, false, true, false>(xh, WVh, Vb, nullptr, nullptr, nullptr, nullptr, S_LEN, DDIM, DDIM, DDIM, DDIM, 0.f);
    rownorm_h_kernel<<<S_LEN, 256>>>(Kb, Kh, DDIM);

    // alpha
    colsum_part<<<dim3(DDIM / 256, 64), 256>>>(x, S_LEN / 64, DDIM);
    colsum_fin<<<DDIM / 256, 256>>>(meanx, 64, DDIM, 1.f / (float)S_LEN);
    alpha_kernel<<<1, 256>>>(aw, ab);

    // forward: h1 (fp32 aux), a1 = silu(h1) -> fp16 only
    run_gemm<MD_DIR, MD_DIR, EPI_SILU, true, false, true>(Kh, W1h, nullptr, A1h, H1, b1, nullptr, S_LEN, DDIM, DDIM, DDIM, DDIM, 0.f);
    // dy_unscaled = a1 W2^T + b2 - v  -> fp32 (colsum) + fp16 (operand)
    run_gemm<MD_DIR, MD_DIR, EPI_DY, false, true, true>(A1h, W2h, DY, DYh, nullptr, b2, Vb, S_LEN, DDIM, DDIM, DDIM, DDIM, 1.f);

    // grads (2/N folded into epilogues / colsum_fin)
    colsum_part<<<dim3(DDIM / 256, 64), 256>>>(DY, S_LEN / 64, DDIM);
    colsum_fin<<<DDIM / 256, 256>>>(gb2, 64, DDIM, dy_scale);
    run_gemm<MD_TRN, MD_TRN, EPI_SCALE, false, true, false>(DYh, A1h, gW2, nullptr, nullptr, nullptr, nullptr, DDIM, DDIM, S_LEN, DDIM, DDIM, dy_scale);
    // dh_unscaled = (dy_unscaled W2) * silu'(h1) -> fp32 + fp16
    run_gemm<MD_DIR, MD_TRN, EPI_DSILU, false, true, true>(DYh, W2h, DH, DHh, nullptr, nullptr, H1, S_LEN, DDIM, DDIM, DDIM, DDIM, 0.f);
    colsum_part<<<dim3(DDIM / 256, 64), 256>>>(DH, S_LEN / 64, DDIM);
    colsum_fin<<<DDIM / 256, 256>>>(gb1, 64, DDIM, dy_scale);
    run_gemm<MD_TRN, MD_TRN, EPI_SCALE, false, true, false>(DHh, Kh, gW1, nullptr, nullptr, nullptr, nullptr, DDIM, DDIM, S_LEN, DDIM, DDIM, dy_scale);

    // fast weights: matrices straight to fp16; biases fp32
    fastw_h_kernel<<<256, 256>>>(W1, gW1, fW1h, DDn);
    fastw_h_kernel<<<256, 256>>>(W2, gW2, fW2h, DDn);
    fastb_kernel<<<2, 256>>>(b1, gb1, fb1, DDIM);
    fastb_kernel<<<2, 256>>>(b2, gb2, fb2, DDIM);

    // retrieve: q = l2norm(x W_Q^T) -> fp16; out = silu(q fW1^T + fb1) fW2^T + fb2
    run_gemm<MD_DIR, MD_DIR, EPI_NONE, false, true, false>(xh, WQh, Qb, nullptr, nullptr, nullptr, nullptr, S_LEN, DDIM, DDIM, DDIM, DDIM, 0.f);
    rownorm_h_kernel<<<S_LEN, 256>>>(Qb, Qh, DDIM);
    run_gemm<MD_DIR, MD_DIR, EPI_SILU, false, false, true>(Qh, fW1h, nullptr, A1h, nullptr, fb1, nullptr, S_LEN, DDIM, DDIM, DDIM, DDIM, 0.f);
    run_gemm<MD_DIR, MD_DIR, EPI_BIAS, false, true, false>(A1h, fW2h, out, nullptr, nullptr, fb2, nullptr, S_LEN, DDIM, DDIM, DDIM, DDIM, 0.f);
}

// round 16
// speedup vs baseline: 6.7141x; 1.1890x over previous
#include <cuda_runtime.h>
#include <cuda_fp16.h>
#include <math.h>
#include <stdint.h>

#define S_LEN 8192
#define DDIM  2048
#define LRATE 0.01f

// ---------------- scratch (static device memory; no allocation) -------------
__device__ float g_scr[5ull * S_LEN * DDIM];
__device__ float g_gW1[DDIM * DDIM];
__device__ float g_gW2[DDIM * DDIM];
__device__ float g_gb1[DDIM], g_gb2[DDIM], g_fb1[DDIM], g_fb2[DDIM];
__device__ float g_meanx[DDIM];
__device__ float g_partial[64 * DDIM];
__device__ float g_alpha;

// fp16 operand buffers
__device__ __half gh_x [(size_t)S_LEN * DDIM];
__device__ __half gh_K [(size_t)S_LEN * DDIM];
__device__ __half gh_Q [(size_t)S_LEN * DDIM];
__device__ __half gh_A1[(size_t)S_LEN * DDIM];   // reused as A2
__device__ __half gh_DY[(size_t)S_LEN * DDIM];
__device__ __half gh_DH[(size_t)S_LEN * DDIM];
__device__ __half gh_WQ[DDIM * DDIM];
__device__ __half gh_WK[DDIM * DDIM];
__device__ __half gh_WV[DDIM * DDIM];
__device__ __half gh_W1[DDIM * DDIM];
__device__ __half gh_W2[DDIM * DDIM];
__device__ __half gh_fW1[DDIM * DDIM];
__device__ __half gh_fW2[DDIM * DDIM];

// ---------------- helpers -----------------------------------------------
__device__ __forceinline__ uint32_t smem_u32(const void* p) {
    uint32_t a;
    asm("{ .reg .u64 t; cvta.to.shared.u64 t, %1; cvt.u32.u64 %0, t; }" : "=r"(a) : "l"(p));
    return a;
}
__device__ __forceinline__ uint32_t pack_h2(__half lo, __half hi) {
    __half2 h = __halves2half2(lo, hi);
    return *reinterpret_cast<uint32_t*>(&h);
}
__device__ __forceinline__ void cp_async16(uint32_t dst, const void* src) {
    asm volatile("cp.async.cg.shared.global [%0], [%1], 16;" :: "r"(dst), "l"(src));
}
__device__ __forceinline__ void cp_commit() { asm volatile("cp.async.commit_group;" ::: "memory"); }
__device__ __forceinline__ void cp_wait0()  { asm volatile("cp.async.wait_group 0;"  ::: "memory"); }

__device__ __forceinline__ void ldsm4(uint32_t (&r)[4], uint32_t addr) {
    asm volatile("ldmatrix.sync.aligned.m8n8.x4.shared.b16 {%0,%1,%2,%3}, [%4];"
                 : "=r"(r[0]), "=r"(r[1]), "=r"(r[2]), "=r"(r[3]) : "r"(addr));
}
__device__ __forceinline__ void mma_f16(float (&c)[4], const uint32_t (&a)[4],
                                        uint32_t b0, uint32_t b1) {
    asm volatile(
        "mma.sync.aligned.m16n8k16.row.col.f32.f16.f16.f32 "
        "{%0,%1,%2,%3}, {%4,%5,%6,%7}, {%8,%9}, {%0,%1,%2,%3};"
        : "+f"(c[0]), "+f"(c[1]), "+f"(c[2]), "+f"(c[3])
        : "r"(a[0]), "r"(a[1]), "r"(a[2]), "r"(a[3]), "r"(b0), "r"(b1));
}

// tile: [128 rows][32 fp16], row stride 64B, 4 chunks of 16B, XOR swizzle
__device__ __forceinline__ uint32_t swz(int row, int ch) {
    return (uint32_t)(row * 64 + ((ch ^ ((row >> 1) & 3)) << 4));
}

// ---------------- GEMM: C[M,N] = A[M,K] * B[N,K]^T ---------------------------
enum { MD_DIR = 0, MD_TRN = 1 };
enum { EPI_NONE = 0, EPI_BIAS = 1, EPI_SILU = 2, EPI_DY = 3, EPI_DSILU = 4, EPI_SCALE = 5 };

// dynamic smem: 2 stages x 16KB; within a stage: A@0 (8KB), B@8192 (8KB)
#define STAGE_BYTES 16384
#define SMEM_BYTES  (2 * STAGE_BYTES)

template <int MODE>
struct Stage {
    uint32_t v[8];   // only used for TRN register staging
    // DIR: cp.async directly into dst tile. TRN: gather into registers.
    __device__ __forceinline__ void issue(const __half* __restrict__ src, int ld,
                                          int org, int k0, int tid, uint32_t dst) {
        if (MODE == MD_DIR) {
#pragma unroll
            for (int i = 0; i < 2; i++) {
                const int f = tid + i * 256, row = f >> 2, ch = f & 3;
                cp_async16(dst + swz(row, ch),
                           src + (size_t)(org + row) * ld + k0 + ch * 8);
            }
        } else {
#pragma unroll
            for (int i = 0; i < 2; i++) {
                const int f = tid + i * 256, r = f & 127, kq = f >> 7;
#pragma unroll
                for (int j = 0; j < 4; j++) {
                    const __half lo = src[(size_t)(k0 + kq * 8 + 2 * j)     * ld + org + r];
                    const __half hi = src[(size_t)(k0 + kq * 8 + 2 * j + 1) * ld + org + r];
                    v[i * 4 + j] = pack_h2(lo, hi);
                }
            }
        }
    }
    __device__ __forceinline__ void finish(uint32_t dst, int tid) {
        if (MODE == MD_TRN) {
#pragma unroll
            for (int i = 0; i < 2; i++) {
                const int f = tid + i * 256, r = f & 127, kq = f >> 7;
                asm volatile("st.shared.v4.b32 [%0], {%1,%2,%3,%4};"
                             :: "r"(dst + swz(r, kq)),
                                "r"(v[i * 4 + 0]), "r"(v[i * 4 + 1]),
                                "r"(v[i * 4 + 2]), "r"(v[i * 4 + 3]));
            }
        }
    }
};

template <int EPI, bool SP>
__device__ __forceinline__ float epi_apply(float a, int cc, size_t idx,
                                           const float* __restrict__ bias,
                                           const float* __restrict__ aux,
                                           float* __restrict__ C2, float scale) {
    if (EPI == EPI_BIAS) {
        a += bias[cc];
    } else if (EPI == EPI_SILU) {
        const float h = a + bias[cc];
        const float sg = 1.f / (1.f + expf(-h));
        if (SP) C2[idx] = h;
        a = h * sg;
    } else if (EPI == EPI_DY) {
        a = scale * (a + bias[cc] - aux[idx]);
    } else if (EPI == EPI_DSILU) {
        const float h = aux[idx];
        const float sg = 1.f / (1.f + expf(-h));
        a = a * (sg * (1.f + h * (1.f - sg)));
    } else if (EPI == EPI_SCALE) {
        a *= scale;
    }
    return a;
}

template <int AM, int BM, int EPI, bool SP, bool WC, bool WH>
__global__ __launch_bounds__(256, 2)
void tc_gemm(const __half* __restrict__ A, const __half* __restrict__ B,
             float* __restrict__ C, __half* __restrict__ Ch,
             float* __restrict__ C2,
             const float* __restrict__ bias, const float* __restrict__ aux,
             int M, int N, int K, int lda, int ldb, float scale)
{
    extern __shared__ char smem[];
    const int tid = threadIdx.x;
    const int lane = tid & 31, wid = tid >> 5;
    const int wm = wid & 1, wn = wid >> 1;          // 2 x 4 warp grid: 64x32 per warp
    const int m0 = blockIdx.y * 128, n0 = blockIdx.x * 128;
    const uint32_t sbase = smem_u32(smem);

    float acc[4][4][4];
#pragma unroll
    for (int a = 0; a < 4; a++)
#pragma unroll
        for (int b = 0; b < 4; b++)
#pragma unroll
            for (int q = 0; q < 4; q++) acc[a][b][q] = 0.f;

    Stage<AM> sa;
    Stage<BM> sb;
    // prologue: stage 0
    sa.issue(A, lda, m0, 0, tid, sbase);
    sb.issue(B, ldb, n0, 0, tid, sbase + 8192);
    cp_commit();
    sa.finish(sbase, tid);
    sb.finish(sbase + 8192, tid);
    cp_wait0();
    __syncthreads();

    const int NC = K >> 5;
    for (int c = 0; c < NC; c++) {
        const uint32_t nb = sbase + (uint32_t)((c + 1) & 1) * STAGE_BYTES;
        if (c + 1 < NC) {
            sa.issue(A, lda, m0, (c + 1) * 32, tid, nb);
            sb.issue(B, ldb, n0, (c + 1) * 32, tid, nb + 8192);
            cp_commit();
        }
        const uint32_t st = sbase + (uint32_t)(c & 1) * STAGE_BYTES;
#pragma unroll
        for (int ks = 0; ks < 2; ks++) {
            uint32_t ah[4][4], bh[2][4];
#pragma unroll
            for (int mt = 0; mt < 4; mt++) {
                const int row = wm * 64 + mt * 16 + (lane & 15);
                const int ch = ks * 2 + (lane >> 4);
                ldsm4(ah[mt], st + swz(row, ch));
            }
#pragma unroll
            for (int p = 0; p < 2; p++) {
                const int row = wn * 32 + p * 16 + ((lane >> 4) << 3) + (lane & 7);
                const int ch = ks * 2 + ((lane >> 3) & 1);
                ldsm4(bh[p], st + 8192u + swz(row, ch));
            }
#pragma unroll
            for (int mt = 0; mt < 4; mt++)
#pragma unroll
                for (int nt = 0; nt < 4; nt++) {
                    const int p = nt >> 1, q = (nt & 1) * 2;
                    mma_f16(acc[mt][nt], ah[mt], bh[p][q], bh[p][q + 1]);
                }
        }
        if (c + 1 < NC) {
            sa.finish(nb, tid);
            sb.finish(nb + 8192, tid);
            cp_wait0();
            __syncthreads();
        }
    }

    // ---- epilogue ----
#pragma unroll
    for (int mt = 0; mt < 4; mt++) {
        const int r0 = m0 + wm * 64 + mt * 16 + (lane >> 2);
#pragma unroll
        for (int nt = 0; nt < 4; nt++) {
            const int cc = n0 + wn * 32 + nt * 8 + (lane & 3) * 2;
            const size_t i0 = (size_t)r0 * N + cc;
            const size_t i1 = (size_t)(r0 + 8) * N + cc;
            float2 t0, t1;
            t0.x = epi_apply<EPI, SP>(acc[mt][nt][0], cc,     i0,     bias, aux, C2, scale);
            t0.y = epi_apply<EPI, SP>(acc[mt][nt][1], cc + 1, i0 + 1, bias, aux, C2, scale);
            t1.x = epi_apply<EPI, SP>(acc[mt][nt][2], cc,     i1,     bias, aux, C2, scale);
            t1.y = epi_apply<EPI, SP>(acc[mt][nt][3], cc + 1, i1 + 1, bias, aux, C2, scale);
            if (WC) {
                *reinterpret_cast<float2*>(C + i0) = t0;
                *reinterpret_cast<float2*>(C + i1) = t1;
            }
            if (WH) {
                __half2 h0 = __floats2half2_rn(t0.x, t0.y);
                __half2 h1 = __floats2half2_rn(t1.x, t1.y);
                *reinterpret_cast<__half2*>(Ch + i0) = h0;
                *reinterpret_cast<__half2*>(Ch + i1) = h1;
            }
        }
    }
}

// ---------------- small kernels ----------------------------------------------
__global__ void f2h_kernel(const float* __restrict__ in, __half* __restrict__ out, int n)
{
    for (int i = blockIdx.x * blockDim.x + threadIdx.x; i < n / 2; i += gridDim.x * blockDim.x) {
        const float2 v = reinterpret_cast<const float2*>(in)[i];
        reinterpret_cast<__half2*>(out)[i] = __floats2half2_rn(v.x, v.y);
    }
}

// row l2-normalize: read fp32, write fp16
__global__ void rownorm_h_kernel(const float* __restrict__ X, __half* __restrict__ out, int ncols)
{
    const int r = blockIdx.x;
    const float* row = X + (size_t)r * ncols;
    float s = 0.f;
    for (int i = threadIdx.x; i < ncols; i += 256) { const float v = row[i]; s += v * v; }
    __shared__ float red[256];
    red[threadIdx.x] = s;
    __syncthreads();
    for (int off = 128; off > 0; off >>= 1) {
        if (threadIdx.x < off) red[threadIdx.x] += red[threadIdx.x + off];
        __syncthreads();
    }
    const float inv = 1.f / fmaxf(sqrtf(red[0]), 1e-12f);
    __half* orow = out + (size_t)r * ncols;
    for (int i = threadIdx.x; i < ncols / 2; i += 256) {
        const float2 v = reinterpret_cast<const float2*>(row)[i];
        reinterpret_cast<__half2*>(orow)[i] = __floats2half2_rn(v.x * inv, v.y * inv);
    }
}

__global__ void colsum_part(const float* __restrict__ X, int rows_per_chunk, int ncols)
{
    const int c = blockIdx.x * blockDim.x + threadIdx.x;
    const int r0 = blockIdx.y * rows_per_chunk;
    float s = 0.f;
    for (int r = 0; r < rows_per_chunk; r++) s += X[(size_t)(r0 + r) * ncols + c];
    g_partial[blockIdx.y * ncols + c] = s;
}

__global__ void colsum_fin(float* __restrict__ out, int nchunks, int ncols, float scale)
{
    const int c = blockIdx.x * blockDim.x + threadIdx.x;
    float s = 0.f;
    for (int i = 0; i < nchunks; i++) s += g_partial[i * ncols + c];
    out[c] = s * scale;
}

__global__ void alpha_kernel(const float* __restrict__ aw, const float* __restrict__ ab)
{
    float s = 0.f;
    for (int i = threadIdx.x; i < DDIM; i += 256) s += g_meanx[i] * aw[i];
    __shared__ float red[256];
    red[threadIdx.x] = s;
    __syncthreads();
    for (int off = 128; off > 0; off >>= 1) {
        if (threadIdx.x < off) red[threadIdx.x] += red[threadIdx.x + off];
        __syncthreads();
    }
    if (threadIdx.x == 0) g_alpha = 1.f / (1.f + expf(-(red[0] + ab[0])));
}

// fast-weight matrices: write fp16 only (consumed exclusively as GEMM operands)
__global__ void fastw_h_kernel(const float* __restrict__ W, const float* __restrict__ g,
                               __half* __restrict__ out, int n)
{
    const float a = g_alpha;
    const float oma = 1.f - a;
    for (int i = blockIdx.x * blockDim.x + threadIdx.x; i < n / 2; i += gridDim.x * blockDim.x) {
        const float2 w = reinterpret_cast<const float2*>(W)[i];
        const float2 gg = reinterpret_cast<const float2*>(g)[i];
        reinterpret_cast<__half2*>(out)[i] =
            __floats2half2_rn(oma * w.x - LRATE * gg.x, oma * w.y - LRATE * gg.y);
    }
}

// fast-weight biases: fp32 (consumed as fp32 bias in epilogues)
__global__ void fastb_kernel(const float* __restrict__ W, const float* __restrict__ g,
                             float* __restrict__ out, int n)
{
    const float a = g_alpha;
    const float oma = 1.f - a;
    for (int i = blockIdx.x * blockDim.x + threadIdx.x; i < n; i += gridDim.x * blockDim.x)
        out[i] = oma * W[i] - LRATE * g[i];
}

// ---------------- host-side launch helpers ----------------------------------
template <int AM, int BM, int EPI, bool SP, bool WC, bool WH>
static void run_gemm(const __half* A, const __half* B, float* C, __half* Ch, float* C2,
                     const float* bias, const float* aux,
                     int M, int N, int K, int lda, int ldb, float scale)
{
    cudaFuncSetAttribute(tc_gemm<AM, BM, EPI, SP, WC, WH>,
                         cudaFuncAttributeMaxDynamicSharedMemorySize, SMEM_BYTES);
    tc_gemm<AM, BM, EPI, SP, WC, WH><<<dim3(N / 128, M / 128), 256, SMEM_BYTES>>>(
        A, B, C, Ch, C2, bias, aux, M, N, K, lda, ldb, scale);
}

extern "C" void kernel_launch(void* const* d_in, const int* in_sizes, int n_in,
                              void* d_out, int out_size)
{
    const float* x  = (const float*)d_in[0];
    const float* WQ = (const float*)d_in[1];
    const float* WK = (const float*)d_in[2];
    const float* WV = (const float*)d_in[3];
    const float* aw = (const float*)d_in[4];
    const float* ab = (const float*)d_in[5];
    const float* W1 = (const float*)d_in[6];
    const float* b1 = (const float*)d_in[7];
    const float* W2 = (const float*)d_in[8];
    const float* b2 = (const float*)d_in[9];
    float* out = (float*)d_out;

    float *scr, *gW1, *gW2, *gb1, *gb2, *fb1, *fb2, *meanx;
    cudaGetSymbolAddress((void**)&scr, g_scr);
    cudaGetSymbolAddress((void**)&gW1, g_gW1);
    cudaGetSymbolAddress((void**)&gW2, g_gW2);
    cudaGetSymbolAddress((void**)&gb1, g_gb1);
    cudaGetSymbolAddress((void**)&gb2, g_gb2);
    cudaGetSymbolAddress((void**)&fb1, g_fb1);
    cudaGetSymbolAddress((void**)&fb2, g_fb2);
    cudaGetSymbolAddress((void**)&meanx, g_meanx);

    __half *xh, *Kh, *Qh, *A1h, *DYh, *DHh, *WQh, *WKh, *WVh, *W1h, *W2h, *fW1h, *fW2h;
    cudaGetSymbolAddress((void**)&xh,  gh_x);
    cudaGetSymbolAddress((void**)&Kh,  gh_K);
    cudaGetSymbolAddress((void**)&Qh,  gh_Q);
    cudaGetSymbolAddress((void**)&A1h, gh_A1);
    cudaGetSymbolAddress((void**)&DYh, gh_DY);
    cudaGetSymbolAddress((void**)&DHh, gh_DH);
    cudaGetSymbolAddress((void**)&WQh, gh_WQ);
    cudaGetSymbolAddress((void**)&WKh, gh_WK);
    cudaGetSymbolAddress((void**)&WVh, gh_WV);
    cudaGetSymbolAddress((void**)&W1h, gh_W1);
    cudaGetSymbolAddress((void**)&W2h, gh_W2);
    cudaGetSymbolAddress((void**)&fW1h, gh_fW1);
    cudaGetSymbolAddress((void**)&fW2h, gh_fW2);

    const size_t SD = (size_t)S_LEN * DDIM;
    float* Kb = scr;            // fp32 k (pre-norm)
    float* Vb = scr + SD;       // fp32 v (aux for EPI_DY)
    float* H1 = scr + 2 * SD;   // fp32 pre-activation (aux for dsilu)
    float* DY = scr + 3 * SD;   // fp32 unscaled dy (colsum gb2)
    float* DH = scr + 4 * SD;   // fp32 unscaled dh (colsum gb1)
    float* Qb = Kb;             // reuse after Kh is produced

    const float dy_scale = 2.f / (float)((size_t)S_LEN * DDIM);
    const int SDn = (int)SD, DDn = DDIM * DDIM;

    // ---- one-time fp16 conversions of external operands (MLP-friendly grids) ----
    f2h_kernel<<<4096, 256>>>(x,  xh,  SDn);
    f2h_kernel<<<1024, 256>>>(WQ, WQh, DDn);
    f2h_kernel<<<1024, 256>>>(WK, WKh, DDn);
    f2h_kernel<<<1024, 256>>>(WV, WVh, DDn);
    f2h_kernel<<<1024, 256>>>(W1, W1h, DDn);
    f2h_kernel<<<1024, 256>>>(W2, W2h, DDn);

    // k = x W_K^T (fp32), v = x W_V^T (fp32)
    run_gemm<MD_DIR, MD_DIR, EPI_NONE, false, true, false>(xh, WKh, Kb, nullptr, nullptr, nullptr, nullptr, S_LEN, DDIM, DDIM, DDIM, DDIM, 0.f);
    run_gemm<MD_DIR, MD_DIR, EPI_NONE, false, true, false>(xh, WVh, Vb, nullptr, nullptr, nullptr, nullptr, S_LEN, DDIM, DDIM, DDIM, DDIM, 0.f);
    rownorm_h_kernel<<<S_LEN, 256>>>(Kb, Kh, DDIM);

    // alpha
    colsum_part<<<dim3(DDIM / 256, 64), 256>>>(x, S_LEN / 64, DDIM);
    colsum_fin<<<DDIM / 256, 256>>>(meanx, 64, DDIM, 1.f / (float)S_LEN);
    alpha_kernel<<<1, 256>>>(aw, ab);

    // forward: h1 (fp32 aux), a1 = silu(h1) -> fp16 only
    run_gemm<MD_DIR, MD_DIR, EPI_SILU, true, false, true>(Kh, W1h, nullptr, A1h, H1, b1, nullptr, S_LEN, DDIM, DDIM, DDIM, DDIM, 0.f);
    // dy_unscaled = a1 W2^T + b2 - v  -> fp32 (colsum) + fp16 (operand)
    run_gemm<MD_DIR, MD_DIR, EPI_DY, false, true, true>(A1h, W2h, DY, DYh, nullptr, b2, Vb, S_LEN, DDIM, DDIM, DDIM, DDIM, 1.f);

    // grads (2/N folded into epilogues / colsum_fin)
    colsum_part<<<dim3(DDIM / 256, 64), 256>>>(DY, S_LEN / 64, DDIM);
    colsum_fin<<<DDIM / 256, 256>>>(gb2, 64, DDIM, dy_scale);
    run_gemm<MD_TRN, MD_TRN, EPI_SCALE, false, true, false>(DYh, A1h, gW2, nullptr, nullptr, nullptr, nullptr, DDIM, DDIM, S_LEN, DDIM, DDIM, dy_scale);
    // dh_unscaled = (dy_unscaled W2) * silu'(h1) -> fp32 + fp16
    run_gemm<MD_DIR, MD_TRN, EPI_DSILU, false, true, true>(DYh, W2h, DH, DHh, nullptr, nullptr, H1, S_LEN, DDIM, DDIM, DDIM, DDIM, 0.f);
    colsum_part<<<dim3(DDIM / 256, 64), 256>>>(DH, S_LEN / 64, DDIM);
    colsum_fin<<<DDIM / 256, 256>>>(gb1, 64, DDIM, dy_scale);
    run_gemm<MD_TRN, MD_TRN, EPI_SCALE, false, true, false>(DHh, Kh, gW1, nullptr, nullptr, nullptr, nullptr, DDIM, DDIM, S_LEN, DDIM, DDIM, dy_scale);

    // fast weights: matrices straight to fp16; biases fp32
    fastw_h_kernel<<<2048, 256>>>(W1, gW1, fW1h, DDn);
    fastw_h_kernel<<<2048, 256>>>(W2, gW2, fW2h, DDn);
    fastb_kernel<<<2, 256>>>(b1, gb1, fb1, DDIM);
    fastb_kernel<<<2, 256>>>(b2, gb2, fb2, DDIM);

    // retrieve: q = l2norm(x W_Q^T) -> fp16; out = silu(q fW1^T + fb1) fW2^T + fb2
    run_gemm<MD_DIR, MD_DIR, EPI_NONE, false, true, false>(xh, WQh, Qb, nullptr, nullptr, nullptr, nullptr, S_LEN, DDIM, DDIM, DDIM, DDIM, 0.f);
    rownorm_h_kernel<<<S_LEN, 256>>>(Qb, Qh, DDIM);
    run_gemm<MD_DIR, MD_DIR, EPI_SILU, false, false, true>(Qh, fW1h, nullptr, A1h, nullptr, fb1, nullptr, S_LEN, DDIM, DDIM, DDIM, DDIM, 0.f);
    run_gemm<MD_DIR, MD_DIR, EPI_BIAS, false, true, false>(A1h, fW2h, out, nullptr, nullptr, fb2, nullptr, S_LEN, DDIM, DDIM, DDIM, DDIM, 0.f);
}

// round 17
// speedup vs baseline: 6.9367x; 1.0332x over previous
#include <cuda_runtime.h>
#include <cuda_fp16.h>
#include <math.h>
#include <stdint.h>

#define S_LEN 8192
#define DDIM  2048
#define LRATE 0.01f

// ---------------- scratch (static device memory; no allocation) -------------
__device__ float g_scr[5ull * S_LEN * DDIM];     // [0:3SD) QKVf fp32, [3SD:4SD) H1
__device__ float g_gW1[DDIM * DDIM];
__device__ float g_gW2[DDIM * DDIM];
__device__ float g_gb1[DDIM], g_gb2[DDIM], g_fb1[DDIM], g_fb2[DDIM];
__device__ float g_meanx[DDIM];
__device__ float g_partX[64 * DDIM];
__device__ float g_partA[64 * DDIM];
__device__ float g_partB[64 * DDIM];
__device__ float g_alpha;

// fp16 operand buffers
__device__ __half gh_x  [(size_t)S_LEN * DDIM];
__device__ __half gh_K  [(size_t)S_LEN * DDIM];
__device__ __half gh_Q  [(size_t)S_LEN * DDIM];
__device__ __half gh_A1 [(size_t)S_LEN * DDIM];   // reused as A2
__device__ __half gh_DY [(size_t)S_LEN * DDIM];
__device__ __half gh_DH [(size_t)S_LEN * DDIM];
__device__ __half gh_QKVw[3ull * DDIM * DDIM];    // [WQ; WK; WV]
__device__ __half gh_W1 [DDIM * DDIM];
__device__ __half gh_W2 [DDIM * DDIM];
__device__ __half gh_fW1[DDIM * DDIM];
__device__ __half gh_fW2[DDIM * DDIM];

// ---------------- helpers -----------------------------------------------
__device__ __forceinline__ uint32_t smem_u32(const void* p) {
    uint32_t a;
    asm("{ .reg .u64 t; cvta.to.shared.u64 t, %1; cvt.u32.u64 %0, t; }" : "=r"(a) : "l"(p));
    return a;
}
__device__ __forceinline__ uint32_t pack_h2(__half lo, __half hi) {
    __half2 h = __halves2half2(lo, hi);
    return *reinterpret_cast<uint32_t*>(&h);
}
__device__ __forceinline__ void cp_async16(uint32_t dst, const void* src) {
    asm volatile("cp.async.cg.shared.global [%0], [%1], 16;" :: "r"(dst), "l"(src));
}
__device__ __forceinline__ void cp_commit() { asm volatile("cp.async.commit_group;" ::: "memory"); }
__device__ __forceinline__ void cp_wait0()  { asm volatile("cp.async.wait_group 0;"  ::: "memory"); }

__device__ __forceinline__ void ldsm4(uint32_t (&r)[4], uint32_t addr) {
    asm volatile("ldmatrix.sync.aligned.m8n8.x4.shared.b16 {%0,%1,%2,%3}, [%4];"
                 : "=r"(r[0]), "=r"(r[1]), "=r"(r[2]), "=r"(r[3]) : "r"(addr));
}
__device__ __forceinline__ void mma_f16(float (&c)[4], const uint32_t (&a)[4],
                                        uint32_t b0, uint32_t b1) {
    asm volatile(
        "mma.sync.aligned.m16n8k16.row.col.f32.f16.f16.f32 "
        "{%0,%1,%2,%3}, {%4,%5,%6,%7}, {%8,%9}, {%0,%1,%2,%3};"
        : "+f"(c[0]), "+f"(c[1]), "+f"(c[2]), "+f"(c[3])
        : "r"(a[0]), "r"(a[1]), "r"(a[2]), "r"(a[3]), "r"(b0), "r"(b1));
}

// tile: [128 rows][64 fp16], row stride 128B, 8 chunks of 16B, 8-way XOR swizzle
__device__ __forceinline__ uint32_t swz(int row, int ch) {
    return (uint32_t)(row * 128 + ((ch ^ (row & 7)) << 4));
}

// ---------------- GEMM: C[M,N] = A[M,K] * B[N,K]^T ---------------------------
enum { MD_DIR = 0, MD_TRN = 1 };
enum { EPI_NONE = 0, EPI_BIAS = 1, EPI_SILU = 2, EPI_DY = 3, EPI_DSILU = 4, EPI_SCALE = 5 };

// dynamic smem: 2 stages x 32KB; within a stage: A@0 (16KB), B@16384 (16KB)
#define STAGE_BYTES 32768
#define SMEM_BYTES  (2 * STAGE_BYTES)

// stage one [128 x 64] fp16 tile. DIR: cp.async (async). TRN: LDG + STS (sync).
template <int MODE>
__device__ __forceinline__ void stage_tile(const __half* __restrict__ src, int ld,
                                           int org, int k0, int tid, uint32_t dst) {
    if (MODE == MD_DIR) {
#pragma unroll
        for (int i = 0; i < 4; i++) {
            const int f = tid + i * 256, row = f >> 3, ch = f & 7;
            cp_async16(dst + swz(row, ch),
                       src + (size_t)(org + row) * ld + k0 + ch * 8);
        }
    } else {
#pragma unroll
        for (int i = 0; i < 4; i++) {
            const int f = tid + i * 256, r = f & 127, kq = f >> 7;
            uint32_t t[4];
#pragma unroll
            for (int j = 0; j < 4; j++) {
                const __half lo = src[(size_t)(k0 + kq * 8 + 2 * j)     * ld + org + r];
                const __half hi = src[(size_t)(k0 + kq * 8 + 2 * j + 1) * ld + org + r];
                t[j] = pack_h2(lo, hi);
            }
            asm volatile("st.shared.v4.b32 [%0], {%1,%2,%3,%4};"
                         :: "r"(dst + swz(r, kq)), "r"(t[0]), "r"(t[1]), "r"(t[2]), "r"(t[3]));
        }
    }
}

template <int EPI, bool SP>
__device__ __forceinline__ float epi_apply(float a, int cc, size_t idx, size_t auxi,
                                           const float* __restrict__ bias,
                                           const float* __restrict__ aux,
                                           float* __restrict__ C2, float scale) {
    if (EPI == EPI_BIAS) {
        a += bias[cc];
    } else if (EPI == EPI_SILU) {
        const float h = a + bias[cc];
        const float sg = 1.f / (1.f + expf(-h));
        if (SP) C2[idx] = h;
        a = h * sg;
    } else if (EPI == EPI_DY) {
        a = scale * (a + bias[cc] - aux[auxi]);
    } else if (EPI == EPI_DSILU) {
        const float h = aux[auxi];
        const float sg = 1.f / (1.f + expf(-h));
        a = a * (sg * (1.f + h * (1.f - sg)));
    } else if (EPI == EPI_SCALE) {
        a *= scale;
    }
    return a;
}

template <int AM, int BM, int EPI, bool SP, bool WC, bool WH, bool CS>
__global__ __launch_bounds__(256, 2)
void tc_gemm(const __half* __restrict__ A, const __half* __restrict__ B,
             float* __restrict__ C, __half* __restrict__ Ch,
             float* __restrict__ C2,
             const float* __restrict__ bias, const float* __restrict__ aux,
             float* __restrict__ colpart,
             int M, int N, int K, int lda, int ldb, int ldaux, float scale)
{
    extern __shared__ char smem[];
    const int tid = threadIdx.x;
    const int lane = tid & 31, wid = tid >> 5;
    const int wm = wid & 1, wn = wid >> 1;          // 2 x 4 warp grid: 64x32 per warp
    const int m0 = blockIdx.y * 128, n0 = blockIdx.x * 128;
    const uint32_t sbase = smem_u32(smem);

    float acc[4][4][4];
#pragma unroll
    for (int a = 0; a < 4; a++)
#pragma unroll
        for (int b = 0; b < 4; b++)
#pragma unroll
            for (int q = 0; q < 4; q++) acc[a][b][q] = 0.f;

    // prologue: stage 0
    stage_tile<AM>(A, lda, m0, 0, tid, sbase);
    stage_tile<BM>(B, ldb, n0, 0, tid, sbase + 16384);
    cp_commit();
    cp_wait0();
    __syncthreads();

    const int NC = K >> 6;
    for (int c = 0; c < NC; c++) {
        const uint32_t nb = sbase + (uint32_t)((c + 1) & 1) * STAGE_BYTES;
        if (c + 1 < NC) {
            stage_tile<AM>(A, lda, m0, (c + 1) * 64, tid, nb);
            stage_tile<BM>(B, ldb, n0, (c + 1) * 64, tid, nb + 16384);
            cp_commit();
        }
        const uint32_t st = sbase + (uint32_t)(c & 1) * STAGE_BYTES;
#pragma unroll
        for (int ks = 0; ks < 4; ks++) {
            uint32_t ah[4][4], bh[2][4];
#pragma unroll
            for (int mt = 0; mt < 4; mt++) {
                const int row = wm * 64 + mt * 16 + (lane & 15);
                const int ch = ks * 2 + (lane >> 4);
                ldsm4(ah[mt], st + swz(row, ch));
            }
#pragma unroll
            for (int p = 0; p < 2; p++) {
                const int row = wn * 32 + p * 16 + ((lane >> 4) << 3) + (lane & 7);
                const int ch = ks * 2 + ((lane >> 3) & 1);
                ldsm4(bh[p], st + 16384u + swz(row, ch));
            }
#pragma unroll
            for (int mt = 0; mt < 4; mt++)
#pragma unroll
                for (int nt = 0; nt < 4; nt++) {
                    const int p = nt >> 1, q = (nt & 1) * 2;
                    mma_f16(acc[mt][nt], ah[mt], bh[p][q], bh[p][q + 1]);
                }
        }
        if (c + 1 < NC) {
            cp_wait0();
            __syncthreads();
        }
    }

    // ---- epilogue ----
    float csum[4][2];
#pragma unroll
    for (int nt = 0; nt < 4; nt++) { csum[nt][0] = 0.f; csum[nt][1] = 0.f; }

#pragma unroll
    for (int mt = 0; mt < 4; mt++) {
        const int r0 = m0 + wm * 64 + mt * 16 + (lane >> 2);
#pragma unroll
        for (int nt = 0; nt < 4; nt++) {
            const int cc = n0 + wn * 32 + nt * 8 + (lane & 3) * 2;
            const size_t i0 = (size_t)r0 * N + cc;
            const size_t i1 = (size_t)(r0 + 8) * N + cc;
            const size_t a0 = (size_t)r0 * ldaux + cc;
            const size_t a1 = (size_t)(r0 + 8) * ldaux + cc;
            float2 t0, t1;
            t0.x = epi_apply<EPI, SP>(acc[mt][nt][0], cc,     i0,     a0,     bias, aux, C2, scale);
            t0.y = epi_apply<EPI, SP>(acc[mt][nt][1], cc + 1, i0 + 1, a0 + 1, bias, aux, C2, scale);
            t1.x = epi_apply<EPI, SP>(acc[mt][nt][2], cc,     i1,     a1,     bias, aux, C2, scale);
            t1.y = epi_apply<EPI, SP>(acc[mt][nt][3], cc + 1, i1 + 1, a1 + 1, bias, aux, C2, scale);
            if (CS) {
                csum[nt][0] += t0.x + t1.x;
                csum[nt][1] += t0.y + t1.y;
            }
            if (WC) {
                *reinterpret_cast<float2*>(C + i0) = t0;
                *reinterpret_cast<float2*>(C + i1) = t1;
            }
            if (WH) {
                *reinterpret_cast<__half2*>(Ch + i0) = __floats2half2_rn(t0.x, t0.y);
                *reinterpret_cast<__half2*>(Ch + i1) = __floats2half2_rn(t1.x, t1.y);
            }
        }
    }

    if (CS) {
        __syncthreads();                       // mainloop smem reads finished
        float* csm = reinterpret_cast<float*>(smem);  // [2 wm][128 cols]
#pragma unroll
        for (int nt = 0; nt < 4; nt++) {
            float c0 = csum[nt][0], c1 = csum[nt][1];
#pragma unroll
            for (int off = 4; off <= 16; off <<= 1) {
                c0 += __shfl_xor_sync(0xffffffffu, c0, off);
                c1 += __shfl_xor_sync(0xffffffffu, c1, off);
            }
            if ((lane >> 2) == 0) {
                const int col = wn * 32 + nt * 8 + (lane & 3) * 2;
                csm[wm * 128 + col]     = c0;
                csm[wm * 128 + col + 1] = c1;
            }
        }
        __syncthreads();
        if (tid < 128)
            colpart[(size_t)blockIdx.y * N + n0 + tid] = csm[tid] + csm[128 + tid];
    }
}

// ---------------- small kernels ----------------------------------------------
__global__ void f2h_kernel(const float* __restrict__ in, __half* __restrict__ out, int n)
{
    for (int i = blockIdx.x * blockDim.x + threadIdx.x; i < n / 2; i += gridDim.x * blockDim.x) {
        const float2 v = reinterpret_cast<const float2*>(in)[i];
        reinterpret_cast<__half2*>(out)[i] = __floats2half2_rn(v.x, v.y);
    }
}

// batched 3-matrix fp32 -> fp16 (QKV weights into one concat buffer)
__global__ void f2h3_kernel(const float* __restrict__ a, const float* __restrict__ b,
                            const float* __restrict__ c, __half* __restrict__ out, int n)
{
    const float* src = (blockIdx.y == 0) ? a : (blockIdx.y == 1) ? b : c;
    __half* dst = out + (size_t)blockIdx.y * n;
    for (int i = blockIdx.x * blockDim.x + threadIdx.x; i < n / 2; i += gridDim.x * blockDim.x) {
        const float2 v = reinterpret_cast<const float2*>(src)[i];
        reinterpret_cast<__half2*>(dst)[i] = __floats2half2_rn(v.x, v.y);
    }
}

// row l2-normalize: read fp32 (ld ldin), write fp16 (ld DDIM)
__global__ void rownorm_h_kernel(const float* __restrict__ X, __half* __restrict__ out,
                                 int ncols, int ldin)
{
    const int r = blockIdx.x;
    const float* row = X + (size_t)r * ldin;
    float s = 0.f;
    for (int i = threadIdx.x; i < ncols; i += 256) { const float v = row[i]; s += v * v; }
    __shared__ float red[256];
    red[threadIdx.x] = s;
    __syncthreads();
    for (int off = 128; off > 0; off >>= 1) {
        if (threadIdx.x < off) red[threadIdx.x] += red[threadIdx.x + off];
        __syncthreads();
    }
    const float inv = 1.f / fmaxf(sqrtf(red[0]), 1e-12f);
    __half* orow = out + (size_t)r * ncols;
    for (int i = threadIdx.x; i < ncols / 2; i += 256) {
        const float2 v = reinterpret_cast<const float2*>(row)[i];
        reinterpret_cast<__half2*>(orow)[i] = __floats2half2_rn(v.x * inv, v.y * inv);
    }
}

__global__ void colsum_part(const float* __restrict__ X, float* __restrict__ part,
                            int rows_per_chunk, int ncols)
{
    const int c = blockIdx.x * blockDim.x + threadIdx.x;
    const int r0 = blockIdx.y * rows_per_chunk;
    float s = 0.f;
    for (int r = 0; r < rows_per_chunk; r++) s += X[(size_t)(r0 + r) * ncols + c];
    part[blockIdx.y * ncols + c] = s;
}

__global__ void colsum_fin(const float* __restrict__ part, float* __restrict__ out,
                           int nchunks, int ncols, float scale)
{
    const int c = blockIdx.x * blockDim.x + threadIdx.x;
    float s = 0.f;
    for (int i = 0; i < nchunks; i++) s += part[i * ncols + c];
    out[c] = s * scale;
}

__global__ void alpha_kernel(const float* __restrict__ aw, const float* __restrict__ ab)
{
    float s = 0.f;
    for (int i = threadIdx.x; i < DDIM; i += 256) s += g_meanx[i] * aw[i];
    __shared__ float red[256];
    red[threadIdx.x] = s;
    __syncthreads();
    for (int off = 128; off > 0; off >>= 1) {
        if (threadIdx.x < off) red[threadIdx.x] += red[threadIdx.x + off];
        __syncthreads();
    }
    if (threadIdx.x == 0) g_alpha = 1.f / (1.f + expf(-(red[0] + ab[0])));
}

__global__ void fastw_h_kernel(const float* __restrict__ W, const float* __restrict__ g,
                               __half* __restrict__ out, int n)
{
    const float a = g_alpha;
    const float oma = 1.f - a;
    for (int i = blockIdx.x * blockDim.x + threadIdx.x; i < n / 2; i += gridDim.x * blockDim.x) {
        const float2 w = reinterpret_cast<const float2*>(W)[i];
        const float2 gg = reinterpret_cast<const float2*>(g)[i];
        reinterpret_cast<__half2*>(out)[i] =
            __floats2half2_rn(oma * w.x - LRATE * gg.x, oma * w.y - LRATE * gg.y);
    }
}

__global__ void fastb_kernel(const float* __restrict__ W, const float* __restrict__ g,
                             float* __restrict__ out, int n)
{
    const float a = g_alpha;
    const float oma = 1.f - a;
    for (int i = blockIdx.x * blockDim.x + threadIdx.x; i < n; i += gridDim.x * blockDim.x)
        out[i] = oma * W[i] - LRATE * g[i];
}

// ---------------- host-side launch helpers ----------------------------------
template <int AM, int BM, int EPI, bool SP, bool WC, bool WH, bool CS>
static void run_gemm(const __half* A, const __half* B, float* C, __half* Ch, float* C2,
                     const float* bias, const float* aux, float* colpart,
                     int M, int N, int K, int lda, int ldb, int ldaux, float scale)
{
    cudaFuncSetAttribute(tc_gemm<AM, BM, EPI, SP, WC, WH, CS>,
                         cudaFuncAttributeMaxDynamicSharedMemorySize, SMEM_BYTES);
    tc_gemm<AM, BM, EPI, SP, WC, WH, CS><<<dim3(N / 128, M / 128), 256, SMEM_BYTES>>>(
        A, B, C, Ch, C2, bias, aux, colpart, M, N, K, lda, ldb, ldaux, scale);
}

extern "C" void kernel_launch(void* const* d_in, const int* in_sizes, int n_in,
                              void* d_out, int out_size)
{
    const float* x  = (const float*)d_in[0];
    const float* WQ = (const float*)d_in[1];
    const float* WK = (const float*)d_in[2];
    const float* WV = (const float*)d_in[3];
    const float* aw = (const float*)d_in[4];
    const float* ab = (const float*)d_in[5];
    const float* W1 = (const float*)d_in[6];
    const float* b1 = (const float*)d_in[7];
    const float* W2 = (const float*)d_in[8];
    const float* b2 = (const float*)d_in[9];
    float* out = (float*)d_out;

    float *scr, *gW1, *gW2, *gb1, *gb2, *fb1, *fb2, *meanx, *pX, *pA, *pB;
    cudaGetSymbolAddress((void**)&scr, g_scr);
    cudaGetSymbolAddress((void**)&gW1, g_gW1);
    cudaGetSymbolAddress((void**)&gW2, g_gW2);
    cudaGetSymbolAddress((void**)&gb1, g_gb1);
    cudaGetSymbolAddress((void**)&gb2, g_gb2);
    cudaGetSymbolAddress((void**)&fb1, g_fb1);
    cudaGetSymbolAddress((void**)&fb2, g_fb2);
    cudaGetSymbolAddress((void**)&meanx, g_meanx);
    cudaGetSymbolAddress((void**)&pX, g_partX);
    cudaGetSymbolAddress((void**)&pA, g_partA);
    cudaGetSymbolAddress((void**)&pB, g_partB);

    __half *xh, *Kh, *Qh, *A1h, *DYh, *DHh, *QKVw, *W1h, *W2h, *fW1h, *fW2h;
    cudaGetSymbolAddress((void**)&xh,   gh_x);
    cudaGetSymbolAddress((void**)&Kh,   gh_K);
    cudaGetSymbolAddress((void**)&Qh,   gh_Q);
    cudaGetSymbolAddress((void**)&A1h,  gh_A1);
    cudaGetSymbolAddress((void**)&DYh,  gh_DY);
    cudaGetSymbolAddress((void**)&DHh,  gh_DH);
    cudaGetSymbolAddress((void**)&QKVw, gh_QKVw);
    cudaGetSymbolAddress((void**)&W1h,  gh_W1);
    cudaGetSymbolAddress((void**)&W2h,  gh_W2);
    cudaGetSymbolAddress((void**)&fW1h, gh_fW1);
    cudaGetSymbolAddress((void**)&fW2h, gh_fW2);

    const size_t SD = (size_t)S_LEN * DDIM;
    float* QKVf = scr;               // [8192, 6144] fp32: Q | K | V
    float* H1   = scr + 3 * SD;      // [8192, 2048] fp32 pre-activation

    const float dy_scale = 2.f / (float)((size_t)S_LEN * DDIM);
    const int SDn = (int)SD, DDn = DDIM * DDIM;
    const int N3 = 3 * DDIM;

    // ---- one-time fp16 conversions ----
    f2h_kernel<<<4096, 256>>>(x, xh, SDn);
    f2h3_kernel<<<dim3(1024, 3), 256>>>(WQ, WK, WV, QKVw, DDn);
    f2h_kernel<<<1024, 256>>>(W1, W1h, DDn);
    f2h_kernel<<<1024, 256>>>(W2, W2h, DDn);

    // batched QKV: [8192, 6144] = x * [WQ; WK; WV]^T
    run_gemm<MD_DIR, MD_DIR, EPI_NONE, false, true, false, false>(
        xh, QKVw, QKVf, nullptr, nullptr, nullptr, nullptr, nullptr,
        S_LEN, N3, DDIM, DDIM, DDIM, N3, 0.f);
    rownorm_h_kernel<<<S_LEN, 256>>>(QKVf + DDIM,     Kh, DDIM, N3);   // K slice
    rownorm_h_kernel<<<S_LEN, 256>>>(QKVf,            Qh, DDIM, N3);   // Q slice (early)

    // alpha
    colsum_part<<<dim3(DDIM / 256, 64), 256>>>(x, pX, S_LEN / 64, DDIM);
    colsum_fin<<<DDIM / 256, 256>>>(pX, meanx, 64, DDIM, 1.f / (float)S_LEN);
    alpha_kernel<<<1, 256>>>(aw, ab);

    // forward: h1 (fp32 aux), a1 = silu(h1) -> fp16
    run_gemm<MD_DIR, MD_DIR, EPI_SILU, true, false, true, false>(
        Kh, W1h, nullptr, A1h, H1, b1, nullptr, nullptr,
        S_LEN, DDIM, DDIM, DDIM, DDIM, DDIM, 0.f);
    // dy_unscaled = a1 W2^T + b2 - v   -> fp16 + fused colsum partials
    run_gemm<MD_DIR, MD_DIR, EPI_DY, false, false, true, true>(
        A1h, W2h, nullptr, DYh, nullptr, b2, QKVf + 2 * DDIM, pA,
        S_LEN, DDIM, DDIM, DDIM, DDIM, N3, 1.f);
    colsum_fin<<<DDIM / 256, 256>>>(pA, gb2, 64, DDIM, dy_scale);

    // gW2 = (2/N) dy^T a1
    run_gemm<MD_TRN, MD_TRN, EPI_SCALE, false, true, false, false>(
        DYh, A1h, gW2, nullptr, nullptr, nullptr, nullptr, nullptr,
        DDIM, DDIM, S_LEN, DDIM, DDIM, DDIM, dy_scale);
    // dh_unscaled = (dy W2) * silu'(h1) -> fp16 + fused colsum partials
    run_gemm<MD_DIR, MD_TRN, EPI_DSILU, false, false, true, true>(
        DYh, W2h, nullptr, DHh, nullptr, nullptr, H1, pB,
        S_LEN, DDIM, DDIM, DDIM, DDIM, DDIM, 0.f);
    colsum_fin<<<DDIM / 256, 256>>>(pB, gb1, 64, DDIM, dy_scale);
    // gW1 = (2/N) dh^T k
    run_gemm<MD_TRN, MD_TRN, EPI_SCALE, false, true, false, false>(
        DHh, Kh, gW1, nullptr, nullptr, nullptr, nullptr, nullptr,
        DDIM, DDIM, S_LEN, DDIM, DDIM, DDIM, dy_scale);

    // fast weights
    fastw_h_kernel<<<2048, 256>>>(W1, gW1, fW1h, DDn);
    fastw_h_kernel<<<2048, 256>>>(W2, gW2, fW2h, DDn);
    fastb_kernel<<<2, 256>>>(b1, gb1, fb1, DDIM);
    fastb_kernel<<<2, 256>>>(b2, gb2, fb2, DDIM);

    // retrieve: out = silu(q fW1^T + fb1) fW2^T + fb2
    run_gemm<MD_DIR, MD_DIR, EPI_SILU, false, false, true, false>(
        Qh, fW1h, nullptr, A1h, nullptr, fb1, nullptr, nullptr,
        S_LEN, DDIM, DDIM, DDIM, DDIM, DDIM, 0.f);
    run_gemm<MD_DIR, MD_DIR, EPI_BIAS, false, true, false, false>(
        A1h, fW2h, out, nullptr, nullptr, fb2, nullptr, nullptr,
        S_LEN, DDIM, DDIM, DDIM, DDIM, DDIM, 0.f);
}